// round 5
// baseline (speedup 1.0000x reference)
#include <cuda_runtime.h>
#include <cstdint>

// ---------------------------------------------------------------------------
// Problem constants
// ---------------------------------------------------------------------------
#define NB     128          // b = B*nw
#define BGLOB  2            // B
#define NW     64           // windows
#define NTOK   343          // n
#define CDIM   512          // c
#define NH     16           // heads
#define HD     32           // head dim
#define NREL   2197
#define MROWS  (NB * NTOK)  // 43904 = 343 * 128
#define SCALE_F 0.17677669529663687f   // 32^-0.5

// ---------------------------------------------------------------------------
// Scratch (device globals; no allocations allowed)
// ---------------------------------------------------------------------------
__device__ float g_k[(size_t)NB * NH * NTOK * HD];     // [b][h][n][d]
__device__ float g_v[(size_t)NB * NH * NTOK * HD];     // [b][h][n][d]
__device__ float g_bias[(size_t)NH * NTOK * NTOK];     // [h][i][j]
__device__ float g_o[(size_t)MROWS * CDIM];            // [b*n][c] head-major cols

// ---------------------------------------------------------------------------
// Kernel 1: relative position bias  bias[h][i][j] = rpb[rel(i,j)*16 + h]
// ---------------------------------------------------------------------------
__global__ void bias_kernel(const float* __restrict__ rpb) {
    int idx = blockIdx.x * 256 + threadIdx.x;
    if (idx >= NTOK * NTOK) return;
    int i = idx / NTOK, j = idx % NTOK;
    int di = i / 49, hi = (i / 7) % 7, wi = i % 7;
    int dj = j / 49, hj = (j / 7) % 7, wj = j % 7;
    int rel = (di - dj + 6) * 169 + (hi - hj + 6) * 13 + (wi - wj + 6);
    const float* src = rpb + rel * NH;
#pragma unroll
    for (int h = 0; h < NH; h++)
        g_bias[(size_t)h * NTOK * NTOK + idx] = src[h];
}

// ---------------------------------------------------------------------------
// Kernel 2/4: SGEMM  C[M,N] = A[M,K] * B[N,K]^T   (A,B row-major)
// BM=BN=128, BK=8, 256 threads, 8x8 micro-tile. Exact tiling (no guards).
// mode 0: KV epilogue -> scatter into g_k / g_v
// mode 1: proj epilogue -> Cout[row*512+col] = acc + cbias[col]
// ---------------------------------------------------------------------------
__global__ __launch_bounds__(256, 2)
void gemm_kernel(const float* __restrict__ Ain,
                 const float* __restrict__ Bw,
                 float* __restrict__ Cout,
                 const float* __restrict__ cbias,
                 int mode) {
    const int K = CDIM;
    const float* A = (mode == 1) ? g_o : Ain;

    __shared__ float As[8][128];
    __shared__ float Bs[8][128];

    int tid = threadIdx.x;
    int tx = tid & 15;           // 0..15  -> col group
    int ty = tid >> 4;           // 0..15  -> row group
    int rowBase = blockIdx.y * 128;
    int colBase = blockIdx.x * 128;

    int lr = tid >> 1;           // 0..127
    int lc = (tid & 1) * 4;      // 0 or 4

    const float* Aptr = A  + (size_t)(rowBase + lr) * K + lc;
    const float* Bptr = Bw + (size_t)(colBase + lr) * K + lc;

    float acc[8][8];
#pragma unroll
    for (int r = 0; r < 8; r++)
#pragma unroll
        for (int c = 0; c < 8; c++) acc[r][c] = 0.f;

    for (int k0 = 0; k0 < K; k0 += 8) {
        float4 av = *(const float4*)(Aptr + k0);
        float4 bv = *(const float4*)(Bptr + k0);
        As[lc + 0][lr] = av.x; As[lc + 1][lr] = av.y;
        As[lc + 2][lr] = av.z; As[lc + 3][lr] = av.w;
        Bs[lc + 0][lr] = bv.x; Bs[lc + 1][lr] = bv.y;
        Bs[lc + 2][lr] = bv.z; Bs[lc + 3][lr] = bv.w;
        __syncthreads();

#pragma unroll
        for (int kk = 0; kk < 8; kk++) {
            float a[8], b[8];
            float4 a0 = *(const float4*)&As[kk][ty * 8];
            float4 a1 = *(const float4*)&As[kk][ty * 8 + 4];
            float4 b0 = *(const float4*)&Bs[kk][tx * 8];
            float4 b1 = *(const float4*)&Bs[kk][tx * 8 + 4];
            a[0]=a0.x; a[1]=a0.y; a[2]=a0.z; a[3]=a0.w;
            a[4]=a1.x; a[5]=a1.y; a[6]=a1.z; a[7]=a1.w;
            b[0]=b0.x; b[1]=b0.y; b[2]=b0.z; b[3]=b0.w;
            b[4]=b1.x; b[5]=b1.y; b[6]=b1.z; b[7]=b1.w;
#pragma unroll
            for (int r = 0; r < 8; r++)
#pragma unroll
                for (int c = 0; c < 8; c++)
                    acc[r][c] = fmaf(a[r], b[c], acc[r][c]);
        }
        __syncthreads();
    }

    if (mode == 0) {
        // KV scatter: col<512 -> K, else V.  row = bb*343 + nn
#pragma unroll
        for (int r = 0; r < 8; r++) {
            int row = rowBase + ty * 8 + r;
            int bb = row / NTOK;
            int nn = row - bb * NTOK;
#pragma unroll
            for (int c = 0; c < 8; c++) {
                int col = colBase + tx * 8 + c;
                int hv  = (col >> 5) & 15;
                int d   = col & 31;
                size_t off = ((((size_t)bb * NH + hv) * NTOK) + nn) * HD + d;
                if (col < 512) g_k[off] = acc[r][c];
                else           g_v[off] = acc[r][c];
            }
        }
    } else {
#pragma unroll
        for (int r = 0; r < 8; r++) {
            int row = rowBase + ty * 8 + r;
#pragma unroll
            for (int c = 0; c < 8; c++) {
                int col = colBase + tx * 8 + c;
                Cout[(size_t)row * CDIM + col] = acc[r][c] + cbias[col];
            }
        }
    }
}

// ---------------------------------------------------------------------------
// Kernel 3: fused attention. One thread per query row; online softmax.
// grid: (b*h = 2048, 3 row-tiles), block 128.
// ---------------------------------------------------------------------------
__global__ __launch_bounds__(128, 4)
void attn_kernel(const float* __restrict__ qg,
                 const float* __restrict__ mask) {
    int bh = blockIdx.x;
    int bb = bh >> 4;
    int h  = bh & 15;
    int Bi = bb >> 6;
    int wi = bb & 63;
    int tid = threadIdx.x;
    int i = blockIdx.y * 128 + tid;
    bool active = (i < NTOK);

    __shared__ float kt[64 * HD];
    __shared__ float vt[64 * HD];

    float4 q[8];
    if (active) {
        const float4* qr = (const float4*)(qg + (((size_t)Bi * NH + h) * NTOK + i) * HD);
#pragma unroll
        for (int d = 0; d < 8; d++) {
            q[d] = qr[d];
            q[d].x *= SCALE_F; q[d].y *= SCALE_F;
            q[d].z *= SCALE_F; q[d].w *= SCALE_F;
        }
    }
    const float* bias_row = g_bias + ((size_t)h * NTOK + (active ? i : 0)) * NTOK;
    const float* mask_row = mask  + ((size_t)wi * NTOK + (active ? i : 0)) * NTOK;
    const float* kbase = g_k + ((size_t)bb * NH + h) * NTOK * HD;
    const float* vbase = g_v + ((size_t)bb * NH + h) * NTOK * HD;

    float mi = -1e30f, li = 0.f;
    float acc[32];
#pragma unroll
    for (int d = 0; d < 32; d++) acc[d] = 0.f;

    for (int m0 = 0; m0 < NTOK; m0 += 64) {
        int mEnd = min(64, NTOK - m0);
        int nElem = mEnd * HD;
        __syncthreads();
        for (int idx = tid * 4; idx < nElem; idx += 128 * 4) {
            *(float4*)&kt[idx] = *(const float4*)&kbase[m0 * HD + idx];
            *(float4*)&vt[idx] = *(const float4*)&vbase[m0 * HD + idx];
        }
        __syncthreads();
        if (!active) continue;

        for (int mm = 0; mm < mEnd; mm++) {
            const float4* k4 = (const float4*)(kt + mm * HD);
            const float4* v4 = (const float4*)(vt + mm * HD);
            float s = __ldg(bias_row + m0 + mm) + __ldg(mask_row + m0 + mm);
#pragma unroll
            for (int d = 0; d < 8; d++) {
                float4 kv = k4[d];
                s = fmaf(q[d].x, kv.x, s);
                s = fmaf(q[d].y, kv.y, s);
                s = fmaf(q[d].z, kv.z, s);
                s = fmaf(q[d].w, kv.w, s);
            }
            if (s <= mi) {
                float p = __expf(s - mi);
                li += p;
#pragma unroll
                for (int d = 0; d < 8; d++) {
                    float4 vv = v4[d];
                    acc[4*d+0] = fmaf(p, vv.x, acc[4*d+0]);
                    acc[4*d+1] = fmaf(p, vv.y, acc[4*d+1]);
                    acc[4*d+2] = fmaf(p, vv.z, acc[4*d+2]);
                    acc[4*d+3] = fmaf(p, vv.w, acc[4*d+3]);
                }
            } else {
                float corr = __expf(mi - s);
                li = fmaf(li, corr, 1.f);
#pragma unroll
                for (int d = 0; d < 8; d++) {
                    float4 vv = v4[d];
                    acc[4*d+0] = fmaf(acc[4*d+0], corr, vv.x);
                    acc[4*d+1] = fmaf(acc[4*d+1], corr, vv.y);
                    acc[4*d+2] = fmaf(acc[4*d+2], corr, vv.z);
                    acc[4*d+3] = fmaf(acc[4*d+3], corr, vv.w);
                }
                mi = s;
            }
        }
    }

    if (active) {
        float inv = 1.f / li;
        float* orow = g_o + ((size_t)bb * NTOK + i) * CDIM + h * HD;
#pragma unroll
        for (int d = 0; d < 32; d++) orow[d] = acc[d] * inv;
    }
}

// ---------------------------------------------------------------------------
// Launch
// ---------------------------------------------------------------------------
extern "C" void kernel_launch(void* const* d_in, const int* in_sizes, int n_in,
                              void* d_out, int out_size) {
    const float* x      = (const float*)d_in[0];
    // d_in[1..3] = D,H,W scalars (constant 7) — unused
    const float* mask   = (const float*)d_in[4];
    const float* qg     = (const float*)d_in[5];
    const float* kv_w   = (const float*)d_in[6];
    const float* proj_w = (const float*)d_in[7];
    const float* proj_b = (const float*)d_in[8];
    const float* rpb    = (const float*)d_in[9];
    float* out = (float*)d_out;

    // 1) bias table
    bias_kernel<<<(NTOK * NTOK + 255) / 256, 256>>>(rpb);

    // 2) KV projection: [43904,512] x [1024,512]^T, scatter into g_k/g_v
    gemm_kernel<<<dim3(1024 / 128, MROWS / 128), 256>>>(x, kv_w, nullptr, nullptr, 0);

    // 3) fused attention -> g_o
    attn_kernel<<<dim3(NB * NH, 3), 128>>>(qg, mask);

    // 4) output projection: [43904,512] x [512,512]^T + bias -> d_out
    gemm_kernel<<<dim3(CDIM / 128, MROWS / 128), 256>>>(nullptr, proj_w, out, proj_b, 1);
}

// round 6
// speedup vs baseline: 1.3511x; 1.3511x over previous
#include <cuda_runtime.h>
#include <cstdint>

// ---------------------------------------------------------------------------
// Problem constants
// ---------------------------------------------------------------------------
#define NB     128          // b = B*nw
#define NTOK   343          // n
#define CDIM   512          // c
#define NH     16           // heads
#define HD     32           // head dim
#define MROWS  (NB * NTOK)  // 43904 = 343 * 128
#define SCALE_F 0.17677669529663687f   // 32^-0.5

// ---------------------------------------------------------------------------
// Scratch (device globals; no allocations allowed)
// ---------------------------------------------------------------------------
__device__ float g_k[(size_t)NB * NH * NTOK * HD];     // [b][h][n][d]
__device__ float g_v[(size_t)NB * NH * NTOK * HD];     // [b][h][n][d]
__device__ float g_bias[(size_t)NH * NTOK * NTOK];     // [h][i][j]
__device__ float g_o[(size_t)MROWS * CDIM];            // [b*n][c] head-major cols

// ---------------------------------------------------------------------------
// Kernel 1: relative position bias  bias[h][i][j] = rpb[rel(i,j)*16 + h]
// ---------------------------------------------------------------------------
__global__ void bias_kernel(const float* __restrict__ rpb) {
    int idx = blockIdx.x * 256 + threadIdx.x;
    if (idx >= NTOK * NTOK) return;
    int i = idx / NTOK, j = idx % NTOK;
    int di = i / 49, hi = (i / 7) % 7, wi = i % 7;
    int dj = j / 49, hj = (j / 7) % 7, wj = j % 7;
    int rel = (di - dj + 6) * 169 + (hi - hj + 6) * 13 + (wi - wj + 6);
    const float* src = rpb + rel * NH;
#pragma unroll
    for (int h = 0; h < NH; h++)
        g_bias[(size_t)h * NTOK * NTOK + idx] = src[h];
}

// ---------------------------------------------------------------------------
// tf32 helpers
// ---------------------------------------------------------------------------
__device__ __forceinline__ float to_tf32(float x) {
    asm("cvt.rna.tf32.f32 %0, %0;" : "+f"(x));
    return x;
}

__device__ __forceinline__ void mma_tf32(float& d0, float& d1, float& d2, float& d3,
                                         uint32_t a0, uint32_t a1, uint32_t a2, uint32_t a3,
                                         uint32_t b0, uint32_t b1) {
    asm volatile(
        "mma.sync.aligned.m16n8k8.row.col.f32.tf32.tf32.f32 "
        "{%0,%1,%2,%3},{%4,%5,%6,%7},{%8,%9},{%0,%1,%2,%3};"
        : "+f"(d0), "+f"(d1), "+f"(d2), "+f"(d3)
        : "r"(a0), "r"(a1), "r"(a2), "r"(a3), "r"(b0), "r"(b1));
}

// ---------------------------------------------------------------------------
// Kernel 2/4: tf32 tensor-core GEMM  C[M,N] = A[M,K] * B[N,K]^T
// BM=BN=128, BK=16, 256 threads (8 warps, 2m x 4n), warp tile 64x32.
// Smem: [k][m] layout, stride 136, XOR swizzle m^((k>>2)*8):
//   conflict-free STS and conflict-free fragment LDS.
// mode 0: KV epilogue -> scatter into g_k / g_v
// mode 1: proj epilogue -> Cout[row*512+col] = acc + cbias[col], A = g_o
// ---------------------------------------------------------------------------
#define GSTR 136

__global__ __launch_bounds__(256)
void gemm_tf32(const float* __restrict__ Ain,
               const float* __restrict__ Bw,
               float* __restrict__ Cout,
               const float* __restrict__ cbias,
               int mode) {
    const float* A = (mode == 1) ? g_o : Ain;

    __shared__ float As[2][16][GSTR];
    __shared__ float Bs[2][16][GSTR];

    const int tid  = threadIdx.x;
    const int warp = tid >> 5;
    const int lane = tid & 31;
    const int qr   = lane >> 2;   // 0..7
    const int qk   = lane & 3;    // 0..3
    const int warpM = (warp & 1) * 64;
    const int warpN = (warp >> 1) * 32;

    const int rowBase = blockIdx.y * 128;
    const int colBase = blockIdx.x * 128;

    // Global load assignment: m0 = tid>>2 (0..63, +64 for second), kq = tid&3
    const int m0 = tid >> 2;
    const int kq = tid & 3;
    const float* a0p = A  + (size_t)(rowBase + m0) * CDIM + kq * 4;
    const float* a1p = a0p + (size_t)64 * CDIM;
    const float* b0p = Bw + (size_t)(colBase + m0) * CDIM + kq * 4;
    const float* b1p = b0p + (size_t)64 * CDIM;
    const int swS = kq << 3;              // store swizzle = (k>>2)*8, k=4*kq+j

    float acc[4][4][4];
#pragma unroll
    for (int mt = 0; mt < 4; mt++)
#pragma unroll
        for (int nt = 0; nt < 4; nt++)
#pragma unroll
            for (int r = 0; r < 4; r++) acc[mt][nt][r] = 0.f;

    float4 ra0, ra1, rb0, rb1;

    // prologue: load + store tile 0
    ra0 = *(const float4*)(a0p); ra1 = *(const float4*)(a1p);
    rb0 = *(const float4*)(b0p); rb1 = *(const float4*)(b1p);
    {
        float av0[4] = {ra0.x, ra0.y, ra0.z, ra0.w};
        float av1[4] = {ra1.x, ra1.y, ra1.z, ra1.w};
        float bv0[4] = {rb0.x, rb0.y, rb0.z, rb0.w};
        float bv1[4] = {rb1.x, rb1.y, rb1.z, rb1.w};
#pragma unroll
        for (int j = 0; j < 4; j++) {
            As[0][kq * 4 + j][m0 ^ swS]        = to_tf32(av0[j]);
            As[0][kq * 4 + j][(m0 + 64) ^ swS] = to_tf32(av1[j]);
            Bs[0][kq * 4 + j][m0 ^ swS]        = to_tf32(bv0[j]);
            Bs[0][kq * 4 + j][(m0 + 64) ^ swS] = to_tf32(bv1[j]);
        }
    }
    __syncthreads();

    for (int it = 0; it < 32; ++it) {
        const int buf = it & 1;
        if (it < 31) {
            const int off = (it + 1) * 16;
            ra0 = *(const float4*)(a0p + off); ra1 = *(const float4*)(a1p + off);
            rb0 = *(const float4*)(b0p + off); rb1 = *(const float4*)(b1p + off);
        }

        // compute two k8 steps from buf
#pragma unroll
        for (int ks = 0; ks < 16; ks += 8) {
            uint32_t af[4][4], bf[4][2];
            const int kA = ks + qk;       // 0..3 or 8..11
            const int kB = ks + qk + 4;   // 4..7 or 12..15
            const int sA = ((kA >> 2) << 3);
            const int sB = ((kB >> 2) << 3);
#pragma unroll
            for (int mt = 0; mt < 4; mt++) {
                const int m = warpM + mt * 16 + qr;
                af[mt][0] = __float_as_uint(As[buf][kA][m ^ sA]);
                af[mt][1] = __float_as_uint(As[buf][kA][(m + 8) ^ sA]);
                af[mt][2] = __float_as_uint(As[buf][kB][m ^ sB]);
                af[mt][3] = __float_as_uint(As[buf][kB][(m + 8) ^ sB]);
            }
#pragma unroll
            for (int nt = 0; nt < 4; nt++) {
                const int nn = warpN + nt * 8 + qr;
                bf[nt][0] = __float_as_uint(Bs[buf][kA][nn ^ sA]);
                bf[nt][1] = __float_as_uint(Bs[buf][kB][nn ^ sB]);
            }
#pragma unroll
            for (int mt = 0; mt < 4; mt++)
#pragma unroll
                for (int nt = 0; nt < 4; nt++)
                    mma_tf32(acc[mt][nt][0], acc[mt][nt][1], acc[mt][nt][2], acc[mt][nt][3],
                             af[mt][0], af[mt][1], af[mt][2], af[mt][3],
                             bf[nt][0], bf[nt][1]);
        }

        if (it < 31) {
            const int nbuf = buf ^ 1;
            float av0[4] = {ra0.x, ra0.y, ra0.z, ra0.w};
            float av1[4] = {ra1.x, ra1.y, ra1.z, ra1.w};
            float bv0[4] = {rb0.x, rb0.y, rb0.z, rb0.w};
            float bv1[4] = {rb1.x, rb1.y, rb1.z, rb1.w};
#pragma unroll
            for (int j = 0; j < 4; j++) {
                As[nbuf][kq * 4 + j][m0 ^ swS]        = to_tf32(av0[j]);
                As[nbuf][kq * 4 + j][(m0 + 64) ^ swS] = to_tf32(av1[j]);
                Bs[nbuf][kq * 4 + j][m0 ^ swS]        = to_tf32(bv0[j]);
                Bs[nbuf][kq * 4 + j][(m0 + 64) ^ swS] = to_tf32(bv1[j]);
            }
        }
        __syncthreads();
    }

    // ----------------------------------------------------------------------
    // Epilogue. Fragment element (reg r): row += (r>=2)*8, col += (r&1).
    // Regs {0,1} and {2,3} are col pairs -> float2 stores.
    // ----------------------------------------------------------------------
    if (mode == 0) {
#pragma unroll
        for (int mt = 0; mt < 4; mt++) {
            const int row = rowBase + warpM + mt * 16 + qr;
            const int bb0 = row / NTOK;
            const int nn0 = row - bb0 * NTOK;
            const int bb8 = (row + 8) / NTOK;
            const int nn8 = (row + 8) - bb8 * NTOK;
#pragma unroll
            for (int nt = 0; nt < 4; nt++) {
                const int col = colBase + warpN + nt * 8 + qk * 2;
                const int hv  = (col >> 5) & 15;
                const int d   = col & 31;
                float* dst = (col < 512) ? g_k : g_v;
                size_t off0 = ((((size_t)bb0 * NH + hv) * NTOK) + nn0) * HD + d;
                size_t off8 = ((((size_t)bb8 * NH + hv) * NTOK) + nn8) * HD + d;
                *(float2*)(dst + off0) = make_float2(acc[mt][nt][0], acc[mt][nt][1]);
                *(float2*)(dst + off8) = make_float2(acc[mt][nt][2], acc[mt][nt][3]);
            }
        }
    } else {
#pragma unroll
        for (int mt = 0; mt < 4; mt++) {
            const int row = rowBase + warpM + mt * 16 + qr;
#pragma unroll
            for (int nt = 0; nt < 4; nt++) {
                const int col = colBase + warpN + nt * 8 + qk * 2;
                const float b0v = cbias[col], b1v = cbias[col + 1];
                *(float2*)(Cout + (size_t)row * CDIM + col) =
                    make_float2(acc[mt][nt][0] + b0v, acc[mt][nt][1] + b1v);
                *(float2*)(Cout + (size_t)(row + 8) * CDIM + col) =
                    make_float2(acc[mt][nt][2] + b0v, acc[mt][nt][3] + b1v);
            }
        }
    }
}

// ---------------------------------------------------------------------------
// Kernel 3: fused attention. One thread per query row; online softmax.
// grid: (b*h = 2048, 3 row-tiles), block 128.
// ---------------------------------------------------------------------------
__global__ __launch_bounds__(128, 4)
void attn_kernel(const float* __restrict__ qg,
                 const float* __restrict__ mask) {
    int bh = blockIdx.x;
    int bb = bh >> 4;
    int h  = bh & 15;
    int Bi = bb >> 6;
    int wi = bb & 63;
    int tid = threadIdx.x;
    int i = blockIdx.y * 128 + tid;
    bool active = (i < NTOK);

    __shared__ float kt[64 * HD];
    __shared__ float vt[64 * HD];

    float4 q[8];
    if (active) {
        const float4* qr = (const float4*)(qg + (((size_t)Bi * NH + h) * NTOK + i) * HD);
#pragma unroll
        for (int d = 0; d < 8; d++) {
            q[d] = qr[d];
            q[d].x *= SCALE_F; q[d].y *= SCALE_F;
            q[d].z *= SCALE_F; q[d].w *= SCALE_F;
        }
    }
    const float* bias_row = g_bias + ((size_t)h * NTOK + (active ? i : 0)) * NTOK;
    const float* mask_row = mask  + ((size_t)wi * NTOK + (active ? i : 0)) * NTOK;
    const float* kbase = g_k + ((size_t)bb * NH + h) * NTOK * HD;
    const float* vbase = g_v + ((size_t)bb * NH + h) * NTOK * HD;

    float mi = -1e30f, li = 0.f;
    float acc[32];
#pragma unroll
    for (int d = 0; d < 32; d++) acc[d] = 0.f;

    for (int m0 = 0; m0 < NTOK; m0 += 64) {
        int mEnd = min(64, NTOK - m0);
        int nElem = mEnd * HD;
        __syncthreads();
        for (int idx = tid * 4; idx < nElem; idx += 128 * 4) {
            *(float4*)&kt[idx] = *(const float4*)&kbase[m0 * HD + idx];
            *(float4*)&vt[idx] = *(const float4*)&vbase[m0 * HD + idx];
        }
        __syncthreads();
        if (!active) continue;

        for (int mm = 0; mm < mEnd; mm++) {
            const float4* k4 = (const float4*)(kt + mm * HD);
            const float4* v4 = (const float4*)(vt + mm * HD);
            float s = __ldg(bias_row + m0 + mm) + __ldg(mask_row + m0 + mm);
#pragma unroll
            for (int d = 0; d < 8; d++) {
                float4 kv = k4[d];
                s = fmaf(q[d].x, kv.x, s);
                s = fmaf(q[d].y, kv.y, s);
                s = fmaf(q[d].z, kv.z, s);
                s = fmaf(q[d].w, kv.w, s);
            }
            if (s <= mi) {
                float p = __expf(s - mi);
                li += p;
#pragma unroll
                for (int d = 0; d < 8; d++) {
                    float4 vv = v4[d];
                    acc[4*d+0] = fmaf(p, vv.x, acc[4*d+0]);
                    acc[4*d+1] = fmaf(p, vv.y, acc[4*d+1]);
                    acc[4*d+2] = fmaf(p, vv.z, acc[4*d+2]);
                    acc[4*d+3] = fmaf(p, vv.w, acc[4*d+3]);
                }
            } else {
                float corr = __expf(mi - s);
                li = fmaf(li, corr, 1.f);
#pragma unroll
                for (int d = 0; d < 8; d++) {
                    float4 vv = v4[d];
                    acc[4*d+0] = fmaf(acc[4*d+0], corr, vv.x);
                    acc[4*d+1] = fmaf(acc[4*d+1], corr, vv.y);
                    acc[4*d+2] = fmaf(acc[4*d+2], corr, vv.z);
                    acc[4*d+3] = fmaf(acc[4*d+3], corr, vv.w);
                }
                mi = s;
            }
        }
    }

    if (active) {
        float inv = 1.f / li;
        float* orow = g_o + ((size_t)bb * NTOK + i) * CDIM + h * HD;
#pragma unroll
        for (int d = 0; d < 32; d++) orow[d] = acc[d] * inv;
    }
}

// ---------------------------------------------------------------------------
// Launch
// ---------------------------------------------------------------------------
extern "C" void kernel_launch(void* const* d_in, const int* in_sizes, int n_in,
                              void* d_out, int out_size) {
    const float* x      = (const float*)d_in[0];
    // d_in[1..3] = D,H,W scalars (constant 7) — unused
    const float* mask   = (const float*)d_in[4];
    const float* qg     = (const float*)d_in[5];
    const float* kv_w   = (const float*)d_in[6];
    const float* proj_w = (const float*)d_in[7];
    const float* proj_b = (const float*)d_in[8];
    const float* rpb    = (const float*)d_in[9];
    float* out = (float*)d_out;

    // 1) bias table
    bias_kernel<<<(NTOK * NTOK + 255) / 256, 256>>>(rpb);

    // 2) KV projection: [43904,512] x [1024,512]^T -> scatter g_k/g_v (tf32 MMA)
    gemm_tf32<<<dim3(1024 / 128, MROWS / 128), 256>>>(x, kv_w, nullptr, nullptr, 0);

    // 3) fused attention -> g_o
    attn_kernel<<<dim3(NB * NH, 3), 128>>>(qg, mask);

    // 4) output projection: [43904,512] x [512,512]^T + bias -> d_out (tf32 MMA)
    gemm_tf32<<<dim3(CDIM / 128, MROWS / 128), 256>>>(nullptr, proj_w, out, proj_b, 1);
}

// round 8
// speedup vs baseline: 2.2056x; 1.6325x over previous
#include <cuda_runtime.h>
#include <cstdint>

// ---------------------------------------------------------------------------
// Problem constants
// ---------------------------------------------------------------------------
#define NB     128          // b = B*nw
#define NTOK   343          // n
#define CDIM   512          // c
#define NH     16           // heads
#define HD     32           // head dim
#define MROWS  (NB * NTOK)  // 43904 = 343 * 128
#define SCALE_F 0.17677669529663687f   // 32^-0.5
#define BMSTR  344          // padded bias/mask row stride (even -> aligned float2)

// ---------------------------------------------------------------------------
// Scratch (device globals; no allocations allowed)
// ---------------------------------------------------------------------------
__device__ float g_k[(size_t)NB * NH * NTOK * HD];       // [b][h][n][d]
__device__ float g_v[(size_t)NB * NH * NTOK * HD];       // [b][h][n][d]
__device__ float g_bias[(size_t)NH * NTOK * BMSTR];      // [h][i][j] stride 344
__device__ float g_maskp[(size_t)64 * NTOK * BMSTR];     // [wi][i][j] stride 344
__device__ float g_o[(size_t)MROWS * CDIM];              // [b*n][c] head-major cols

// ---------------------------------------------------------------------------
// Kernel 1a: relative position bias  bias[h][i][j] = rpb[rel(i,j)*16 + h]
// (padded stride 344, pad col zeroed)
// ---------------------------------------------------------------------------
__global__ void bias_kernel(const float* __restrict__ rpb) {
    int idx = blockIdx.x * 256 + threadIdx.x;
    if (idx >= NTOK * BMSTR) return;
    int i = idx / BMSTR, j = idx % BMSTR;
    if (j >= NTOK) {
#pragma unroll
        for (int h = 0; h < NH; h++)
            g_bias[(size_t)h * NTOK * BMSTR + idx] = 0.f;
        return;
    }
    int di = i / 49, hi = (i / 7) % 7, wi = i % 7;
    int dj = j / 49, hj = (j / 7) % 7, wj = j % 7;
    int rel = (di - dj + 6) * 169 + (hi - hj + 6) * 13 + (wi - wj + 6);
    const float* src = rpb + rel * NH;
#pragma unroll
    for (int h = 0; h < NH; h++)
        g_bias[(size_t)h * NTOK * BMSTR + idx] = src[h];
}

// ---------------------------------------------------------------------------
// Kernel 1b: repack mask into padded stride-344 table
// ---------------------------------------------------------------------------
__global__ void mask_copy_kernel(const float* __restrict__ mask) {
    int idx = blockIdx.x * 256 + threadIdx.x;
    if (idx >= 64 * NTOK * BMSTR) return;
    int w = idx / (NTOK * BMSTR);
    int r = idx % (NTOK * BMSTR);
    int i = r / BMSTR, j = r % BMSTR;
    g_maskp[idx] = (j < NTOK) ? mask[((size_t)w * NTOK + i) * NTOK + j] : 0.f;
}

// ---------------------------------------------------------------------------
// tf32 helpers
// ---------------------------------------------------------------------------
__device__ __forceinline__ float to_tf32(float x) {
    asm("cvt.rna.tf32.f32 %0, %0;" : "+f"(x));
    return x;
}

__device__ __forceinline__ void mma_tf32(float& d0, float& d1, float& d2, float& d3,
                                         uint32_t a0, uint32_t a1, uint32_t a2, uint32_t a3,
                                         uint32_t b0, uint32_t b1) {
    asm volatile(
        "mma.sync.aligned.m16n8k8.row.col.f32.tf32.tf32.f32 "
        "{%0,%1,%2,%3},{%4,%5,%6,%7},{%8,%9},{%0,%1,%2,%3};"
        : "+f"(d0), "+f"(d1), "+f"(d2), "+f"(d3)
        : "r"(a0), "r"(a1), "r"(a2), "r"(a3), "r"(b0), "r"(b1));
}

// ---------------------------------------------------------------------------
// Kernel 2/4: tf32 tensor-core GEMM  C[M,N] = A[M,K] * B[N,K]^T
// (unchanged from round 5)
// ---------------------------------------------------------------------------
#define GSTR 136

__global__ __launch_bounds__(256)
void gemm_tf32(const float* __restrict__ Ain,
               const float* __restrict__ Bw,
               float* __restrict__ Cout,
               const float* __restrict__ cbias,
               int mode) {
    const float* A = (mode == 1) ? g_o : Ain;

    __shared__ float As[2][16][GSTR];
    __shared__ float Bs[2][16][GSTR];

    const int tid  = threadIdx.x;
    const int warp = tid >> 5;
    const int lane = tid & 31;
    const int qr   = lane >> 2;   // 0..7
    const int qk   = lane & 3;    // 0..3
    const int warpM = (warp & 1) * 64;
    const int warpN = (warp >> 1) * 32;

    const int rowBase = blockIdx.y * 128;
    const int colBase = blockIdx.x * 128;

    const int m0 = tid >> 2;
    const int kq = tid & 3;
    const float* a0p = A  + (size_t)(rowBase + m0) * CDIM + kq * 4;
    const float* a1p = a0p + (size_t)64 * CDIM;
    const float* b0p = Bw + (size_t)(colBase + m0) * CDIM + kq * 4;
    const float* b1p = b0p + (size_t)64 * CDIM;
    const int swS = kq << 3;

    float acc[4][4][4];
#pragma unroll
    for (int mt = 0; mt < 4; mt++)
#pragma unroll
        for (int nt = 0; nt < 4; nt++)
#pragma unroll
            for (int r = 0; r < 4; r++) acc[mt][nt][r] = 0.f;

    float4 ra0, ra1, rb0, rb1;

    ra0 = *(const float4*)(a0p); ra1 = *(const float4*)(a1p);
    rb0 = *(const float4*)(b0p); rb1 = *(const float4*)(b1p);
    {
        float av0[4] = {ra0.x, ra0.y, ra0.z, ra0.w};
        float av1[4] = {ra1.x, ra1.y, ra1.z, ra1.w};
        float bv0[4] = {rb0.x, rb0.y, rb0.z, rb0.w};
        float bv1[4] = {rb1.x, rb1.y, rb1.z, rb1.w};
#pragma unroll
        for (int j = 0; j < 4; j++) {
            As[0][kq * 4 + j][m0 ^ swS]        = to_tf32(av0[j]);
            As[0][kq * 4 + j][(m0 + 64) ^ swS] = to_tf32(av1[j]);
            Bs[0][kq * 4 + j][m0 ^ swS]        = to_tf32(bv0[j]);
            Bs[0][kq * 4 + j][(m0 + 64) ^ swS] = to_tf32(bv1[j]);
        }
    }
    __syncthreads();

    for (int it = 0; it < 32; ++it) {
        const int buf = it & 1;
        if (it < 31) {
            const int off = (it + 1) * 16;
            ra0 = *(const float4*)(a0p + off); ra1 = *(const float4*)(a1p + off);
            rb0 = *(const float4*)(b0p + off); rb1 = *(const float4*)(b1p + off);
        }

#pragma unroll
        for (int ks = 0; ks < 16; ks += 8) {
            uint32_t af[4][4], bf[4][2];
            const int kA = ks + qk;
            const int kB = ks + qk + 4;
            const int sA = ((kA >> 2) << 3);
            const int sB = ((kB >> 2) << 3);
#pragma unroll
            for (int mt = 0; mt < 4; mt++) {
                const int m = warpM + mt * 16 + qr;
                af[mt][0] = __float_as_uint(As[buf][kA][m ^ sA]);
                af[mt][1] = __float_as_uint(As[buf][kA][(m + 8) ^ sA]);
                af[mt][2] = __float_as_uint(As[buf][kB][m ^ sB]);
                af[mt][3] = __float_as_uint(As[buf][kB][(m + 8) ^ sB]);
            }
#pragma unroll
            for (int nt = 0; nt < 4; nt++) {
                const int nn = warpN + nt * 8 + qr;
                bf[nt][0] = __float_as_uint(Bs[buf][kA][nn ^ sA]);
                bf[nt][1] = __float_as_uint(Bs[buf][kB][nn ^ sB]);
            }
#pragma unroll
            for (int mt = 0; mt < 4; mt++)
#pragma unroll
                for (int nt = 0; nt < 4; nt++)
                    mma_tf32(acc[mt][nt][0], acc[mt][nt][1], acc[mt][nt][2], acc[mt][nt][3],
                             af[mt][0], af[mt][1], af[mt][2], af[mt][3],
                             bf[nt][0], bf[nt][1]);
        }

        if (it < 31) {
            const int nbuf = buf ^ 1;
            float av0[4] = {ra0.x, ra0.y, ra0.z, ra0.w};
            float av1[4] = {ra1.x, ra1.y, ra1.z, ra1.w};
            float bv0[4] = {rb0.x, rb0.y, rb0.z, rb0.w};
            float bv1[4] = {rb1.x, rb1.y, rb1.z, rb1.w};
#pragma unroll
            for (int j = 0; j < 4; j++) {
                As[nbuf][kq * 4 + j][m0 ^ swS]        = to_tf32(av0[j]);
                As[nbuf][kq * 4 + j][(m0 + 64) ^ swS] = to_tf32(av1[j]);
                Bs[nbuf][kq * 4 + j][m0 ^ swS]        = to_tf32(bv0[j]);
                Bs[nbuf][kq * 4 + j][(m0 + 64) ^ swS] = to_tf32(bv1[j]);
            }
        }
        __syncthreads();
    }

    if (mode == 0) {
#pragma unroll
        for (int mt = 0; mt < 4; mt++) {
            const int row = rowBase + warpM + mt * 16 + qr;
            const int bb0 = row / NTOK;
            const int nn0 = row - bb0 * NTOK;
            const int bb8 = (row + 8) / NTOK;
            const int nn8 = (row + 8) - bb8 * NTOK;
#pragma unroll
            for (int nt = 0; nt < 4; nt++) {
                const int col = colBase + warpN + nt * 8 + qk * 2;
                const int hv  = (col >> 5) & 15;
                const int d   = col & 31;
                float* dst = (col < 512) ? g_k : g_v;
                size_t off0 = ((((size_t)bb0 * NH + hv) * NTOK) + nn0) * HD + d;
                size_t off8 = ((((size_t)bb8 * NH + hv) * NTOK) + nn8) * HD + d;
                *(float2*)(dst + off0) = make_float2(acc[mt][nt][0], acc[mt][nt][1]);
                *(float2*)(dst + off8) = make_float2(acc[mt][nt][2], acc[mt][nt][3]);
            }
        }
    } else {
#pragma unroll
        for (int mt = 0; mt < 4; mt++) {
            const int row = rowBase + warpM + mt * 16 + qr;
#pragma unroll
            for (int nt = 0; nt < 4; nt++) {
                const int col = colBase + warpN + nt * 8 + qk * 2;
                const float b0v = cbias[col], b1v = cbias[col + 1];
                *(float2*)(Cout + (size_t)row * CDIM + col) =
                    make_float2(acc[mt][nt][0] + b0v, acc[mt][nt][1] + b1v);
                *(float2*)(Cout + (size_t)(row + 8) * CDIM + col) =
                    make_float2(acc[mt][nt][2] + b0v, acc[mt][nt][3] + b1v);
            }
        }
    }
}

// ---------------------------------------------------------------------------
// Kernel 3: tensor-core flash attention.
// grid (b*h = 2048, 3 query tiles of 128), block 256 (8 warps).
// Each warp owns 16 query rows -> softmax is warp-local (quad shuffles).
// Per 64-key chunk: S = Q K^T (mma tf32), +bias+mask, online softmax,
// P -> per-warp smem slab, O += P V (mma tf32).
// smem: K [64][36] + V [64][36] + P 8*[16][68]  = 53248 B (dynamic)
// ---------------------------------------------------------------------------
#define KSTR 36
#define PSTR 68
#define ATT_SMEM ((2 * 64 * KSTR + 8 * 16 * PSTR) * 4)

__global__ __launch_bounds__(256)
void attn_mma(const float* __restrict__ qg) {
    const int bh = blockIdx.x;
    const int bb = bh >> 4, h = bh & 15;
    const int Bi = bb >> 6, wi = bb & 63;
    const int qbase = blockIdx.y * 128;
    const int tid = threadIdx.x, warp = tid >> 5, lane = tid & 31;
    const int g = lane >> 2, t = lane & 3;

    extern __shared__ float sm[];
    float* Ks = sm;                               // [64][36]
    float* Vs = sm + 64 * KSTR;                   // [64][36]
    float* Ps = sm + 2 * 64 * KSTR + warp * (16 * PSTR);  // warp slab [16][68]

    const int r0 = qbase + warp * 16 + g;
    const int r1 = r0 + 8;
    const int r0c = min(r0, NTOK - 1), r1c = min(r1, NTOK - 1);

    // Q fragments (held in registers for the whole kernel), pre-scaled
    const float* q0p = qg + (((size_t)Bi * NH + h) * NTOK + r0c) * HD;
    const float* q1p = qg + (((size_t)Bi * NH + h) * NTOK + r1c) * HD;
    uint32_t qa[4][4];
#pragma unroll
    for (int ks = 0; ks < 4; ks++) {
        qa[ks][0] = __float_as_uint(to_tf32(q0p[ks * 8 + t] * SCALE_F));
        qa[ks][1] = __float_as_uint(to_tf32(q1p[ks * 8 + t] * SCALE_F));
        qa[ks][2] = __float_as_uint(to_tf32(q0p[ks * 8 + t + 4] * SCALE_F));
        qa[ks][3] = __float_as_uint(to_tf32(q1p[ks * 8 + t + 4] * SCALE_F));
    }

    const float* brow0 = g_bias  + ((size_t)h  * NTOK + r0c) * BMSTR;
    const float* brow1 = g_bias  + ((size_t)h  * NTOK + r1c) * BMSTR;
    const float* mrow0 = g_maskp + ((size_t)wi * NTOK + r0c) * BMSTR;
    const float* mrow1 = g_maskp + ((size_t)wi * NTOK + r1c) * BMSTR;

    const float* kb = g_k + ((size_t)bb * NH + h) * NTOK * HD;
    const float* vb = g_v + ((size_t)bb * NH + h) * NTOK * HD;

    float rm0 = -1e30f, rm1 = -1e30f, l0 = 0.f, l1 = 0.f;
    float oacc[4][4];
#pragma unroll
    for (int df = 0; df < 4; df++)
#pragma unroll
        for (int r = 0; r < 4; r++) oacc[df][r] = 0.f;

    const int ln = tid >> 2;           // 0..63: K/V row to load
    const int lp = (tid & 3) * 8;      // 8-float segment

    for (int c = 0; c < 6; c++) {
        const int kb0 = c * 64;
        __syncthreads();
        // stage K,V chunk (tf32-converted)
        {
            int gn = min(kb0 + ln, NTOK - 1);
            float4 x0 = *(const float4*)(kb + (size_t)gn * HD + lp);
            float4 x1 = *(const float4*)(kb + (size_t)gn * HD + lp + 4);
            float4 y0 = *(const float4*)(vb + (size_t)gn * HD + lp);
            float4 y1 = *(const float4*)(vb + (size_t)gn * HD + lp + 4);
            x0.x = to_tf32(x0.x); x0.y = to_tf32(x0.y); x0.z = to_tf32(x0.z); x0.w = to_tf32(x0.w);
            x1.x = to_tf32(x1.x); x1.y = to_tf32(x1.y); x1.z = to_tf32(x1.z); x1.w = to_tf32(x1.w);
            y0.x = to_tf32(y0.x); y0.y = to_tf32(y0.y); y0.z = to_tf32(y0.z); y0.w = to_tf32(y0.w);
            y1.x = to_tf32(y1.x); y1.y = to_tf32(y1.y); y1.z = to_tf32(y1.z); y1.w = to_tf32(y1.w);
            *(float4*)(Ks + ln * KSTR + lp)     = x0;
            *(float4*)(Ks + ln * KSTR + lp + 4) = x1;
            *(float4*)(Vs + ln * KSTR + lp)     = y0;
            *(float4*)(Vs + ln * KSTR + lp + 4) = y1;
        }
        __syncthreads();

        // S = Q K^T : 8 n-frags x 4 k-steps
        float sacc[8][4];
#pragma unroll
        for (int nf = 0; nf < 8; nf++)
#pragma unroll
            for (int r = 0; r < 4; r++) sacc[nf][r] = 0.f;
#pragma unroll
        for (int ks = 0; ks < 4; ks++) {
#pragma unroll
            for (int nf = 0; nf < 8; nf++) {
                uint32_t b0 = __float_as_uint(Ks[(nf * 8 + g) * KSTR + ks * 8 + t]);
                uint32_t b1 = __float_as_uint(Ks[(nf * 8 + g) * KSTR + ks * 8 + t + 4]);
                mma_tf32(sacc[nf][0], sacc[nf][1], sacc[nf][2], sacc[nf][3],
                         qa[ks][0], qa[ks][1], qa[ks][2], qa[ks][3], b0, b1);
            }
        }

        // + bias + mask, OOB -> -inf, chunk row max
        float cm0 = -1e30f, cm1 = -1e30f;
#pragma unroll
        for (int nf = 0; nf < 8; nf++) {
            int col = kb0 + nf * 8 + 2 * t;
            float2 bv0 = *(const float2*)(brow0 + col);
            float2 mv0 = *(const float2*)(mrow0 + col);
            float2 bv1 = *(const float2*)(brow1 + col);
            float2 mv1 = *(const float2*)(mrow1 + col);
            sacc[nf][0] = (col     < NTOK) ? sacc[nf][0] + bv0.x + mv0.x : -1e30f;
            sacc[nf][1] = (col + 1 < NTOK) ? sacc[nf][1] + bv0.y + mv0.y : -1e30f;
            sacc[nf][2] = (col     < NTOK) ? sacc[nf][2] + bv1.x + mv1.x : -1e30f;
            sacc[nf][3] = (col + 1 < NTOK) ? sacc[nf][3] + bv1.y + mv1.y : -1e30f;
            cm0 = fmaxf(cm0, fmaxf(sacc[nf][0], sacc[nf][1]));
            cm1 = fmaxf(cm1, fmaxf(sacc[nf][2], sacc[nf][3]));
        }
        cm0 = fmaxf(cm0, __shfl_xor_sync(0xffffffffu, cm0, 1));
        cm0 = fmaxf(cm0, __shfl_xor_sync(0xffffffffu, cm0, 2));
        cm1 = fmaxf(cm1, __shfl_xor_sync(0xffffffffu, cm1, 1));
        cm1 = fmaxf(cm1, __shfl_xor_sync(0xffffffffu, cm1, 2));

        float mn0 = fmaxf(rm0, cm0), mn1 = fmaxf(rm1, cm1);
        float sc0 = __expf(rm0 - mn0), sc1 = __expf(rm1 - mn1);
        rm0 = mn0; rm1 = mn1;

        float ls0 = 0.f, ls1 = 0.f;
#pragma unroll
        for (int nf = 0; nf < 8; nf++) {
            float p0 = __expf(sacc[nf][0] - mn0);
            float p1 = __expf(sacc[nf][1] - mn0);
            float p2 = __expf(sacc[nf][2] - mn1);
            float p3 = __expf(sacc[nf][3] - mn1);
            ls0 += p0 + p1; ls1 += p2 + p3;
            *(float2*)(Ps + g * PSTR       + nf * 8 + 2 * t) = make_float2(to_tf32(p0), to_tf32(p1));
            *(float2*)(Ps + (g + 8) * PSTR + nf * 8 + 2 * t) = make_float2(to_tf32(p2), to_tf32(p3));
        }
        ls0 += __shfl_xor_sync(0xffffffffu, ls0, 1);
        ls0 += __shfl_xor_sync(0xffffffffu, ls0, 2);
        ls1 += __shfl_xor_sync(0xffffffffu, ls1, 1);
        ls1 += __shfl_xor_sync(0xffffffffu, ls1, 2);
        l0 = l0 * sc0 + ls0;
        l1 = l1 * sc1 + ls1;

#pragma unroll
        for (int df = 0; df < 4; df++) {
            oacc[df][0] *= sc0; oacc[df][1] *= sc0;
            oacc[df][2] *= sc1; oacc[df][3] *= sc1;
        }
        __syncwarp();

        // O += P V : 8 k-steps x 4 d-frags
#pragma unroll
        for (int ks = 0; ks < 8; ks++) {
            uint32_t a0 = __float_as_uint(Ps[g * PSTR       + ks * 8 + t]);
            uint32_t a1 = __float_as_uint(Ps[(g + 8) * PSTR + ks * 8 + t]);
            uint32_t a2 = __float_as_uint(Ps[g * PSTR       + ks * 8 + t + 4]);
            uint32_t a3 = __float_as_uint(Ps[(g + 8) * PSTR + ks * 8 + t + 4]);
#pragma unroll
            for (int df = 0; df < 4; df++) {
                uint32_t b0 = __float_as_uint(Vs[(ks * 8 + t) * KSTR + df * 8 + g]);
                uint32_t b1 = __float_as_uint(Vs[(ks * 8 + t + 4) * KSTR + df * 8 + g]);
                mma_tf32(oacc[df][0], oacc[df][1], oacc[df][2], oacc[df][3],
                         a0, a1, a2, a3, b0, b1);
            }
        }
        __syncwarp();
    }

    // epilogue: normalize + store
    float inv0 = 1.f / l0, inv1 = 1.f / l1;
    if (r0 < NTOK) {
        float* orow = g_o + ((size_t)bb * NTOK + r0) * CDIM + h * HD;
#pragma unroll
        for (int df = 0; df < 4; df++)
            *(float2*)(orow + df * 8 + 2 * t) =
                make_float2(oacc[df][0] * inv0, oacc[df][1] * inv0);
    }
    if (r1 < NTOK) {
        float* orow = g_o + ((size_t)bb * NTOK + r1) * CDIM + h * HD;
#pragma unroll
        for (int df = 0; df < 4; df++)
            *(float2*)(orow + df * 8 + 2 * t) =
                make_float2(oacc[df][2] * inv1, oacc[df][3] * inv1);
    }
}

// ---------------------------------------------------------------------------
// Launch
// ---------------------------------------------------------------------------
extern "C" void kernel_launch(void* const* d_in, const int* in_sizes, int n_in,
                              void* d_out, int out_size) {
    const float* x      = (const float*)d_in[0];
    // d_in[1..3] = D,H,W scalars (constant 7) — unused
    const float* mask   = (const float*)d_in[4];
    const float* qg     = (const float*)d_in[5];
    const float* kv_w   = (const float*)d_in[6];
    const float* proj_w = (const float*)d_in[7];
    const float* proj_b = (const float*)d_in[8];
    const float* rpb    = (const float*)d_in[9];
    float* out = (float*)d_out;

    cudaFuncSetAttribute(attn_mma, cudaFuncAttributeMaxDynamicSharedMemorySize, ATT_SMEM);

    // 1) padded bias + mask tables
    bias_kernel<<<(NTOK * BMSTR + 255) / 256, 256>>>(rpb);
    mask_copy_kernel<<<(64 * NTOK * BMSTR + 255) / 256, 256>>>(mask);

    // 2) KV projection: [43904,512] x [1024,512]^T -> scatter g_k/g_v (tf32 MMA)
    gemm_tf32<<<dim3(1024 / 128, MROWS / 128), 256>>>(x, kv_w, nullptr, nullptr, 0);

    // 3) tensor-core flash attention -> g_o
    attn_mma<<<dim3(NB * NH, 3), 256, ATT_SMEM>>>(qg);

    // 4) output projection: [43904,512] x [512,512]^T + bias -> d_out (tf32 MMA)
    gemm_tf32<<<dim3(CDIM / 128, MROWS / 128), 256>>>(nullptr, proj_w, out, proj_b, 1);
}

// round 9
// speedup vs baseline: 2.8659x; 1.2993x over previous
#include <cuda_runtime.h>
#include <cstdint>

// ---------------------------------------------------------------------------
// Problem constants
// ---------------------------------------------------------------------------
#define NB     128          // b = B*nw
#define NTOK   343          // n
#define CDIM   512          // c
#define NH     16           // heads
#define HD     32           // head dim
#define MROWS  (NB * NTOK)  // 43904 = 343 * 128
#define SCALE_F 0.17677669529663687f   // 32^-0.5
#define BMSTR  344          // padded bias/mask row stride (even -> aligned float2)

// ---------------------------------------------------------------------------
// Scratch (device globals; no allocations allowed)
// ---------------------------------------------------------------------------
__device__ float g_k[(size_t)NB * NH * NTOK * HD];       // [b][h][n][d]  (tf32-rounded)
__device__ float g_v[(size_t)NB * NH * NTOK * HD];       // [b][h][n][d]  (tf32-rounded)
__device__ float g_bias[(size_t)NH * NTOK * BMSTR];      // [h][i][j] stride 344
__device__ float g_maskp[(size_t)64 * NTOK * BMSTR];     // [wi][i][j] stride 344
__device__ float g_o[(size_t)MROWS * CDIM];              // [b*n][c] head-major cols

// ---------------------------------------------------------------------------
// Kernel 1a: relative position bias  bias[h][i][j] = rpb[rel(i,j)*16 + h]
// ---------------------------------------------------------------------------
__global__ void bias_kernel(const float* __restrict__ rpb) {
    int idx = blockIdx.x * 256 + threadIdx.x;
    if (idx >= NTOK * BMSTR) return;
    int i = idx / BMSTR, j = idx % BMSTR;
    if (j >= NTOK) {
#pragma unroll
        for (int h = 0; h < NH; h++)
            g_bias[(size_t)h * NTOK * BMSTR + idx] = 0.f;
        return;
    }
    int di = i / 49, hi = (i / 7) % 7, wi = i % 7;
    int dj = j / 49, hj = (j / 7) % 7, wj = j % 7;
    int rel = (di - dj + 6) * 169 + (hi - hj + 6) * 13 + (wi - wj + 6);
    const float* src = rpb + rel * NH;
#pragma unroll
    for (int h = 0; h < NH; h++)
        g_bias[(size_t)h * NTOK * BMSTR + idx] = src[h];
}

// ---------------------------------------------------------------------------
// Kernel 1b: repack mask into padded stride-344 table
// ---------------------------------------------------------------------------
__global__ void mask_copy_kernel(const float* __restrict__ mask) {
    int idx = blockIdx.x * 256 + threadIdx.x;
    if (idx >= 64 * NTOK * BMSTR) return;
    int w = idx / (NTOK * BMSTR);
    int r = idx % (NTOK * BMSTR);
    int i = r / BMSTR, j = r % BMSTR;
    g_maskp[idx] = (j < NTOK) ? mask[((size_t)w * NTOK + i) * NTOK + j] : 0.f;
}

// ---------------------------------------------------------------------------
// tf32 / cp.async helpers
// ---------------------------------------------------------------------------
__device__ __forceinline__ float to_tf32(float x) {
    asm("cvt.rna.tf32.f32 %0, %0;" : "+f"(x));
    return x;
}

__device__ __forceinline__ void mma_tf32(float& d0, float& d1, float& d2, float& d3,
                                         uint32_t a0, uint32_t a1, uint32_t a2, uint32_t a3,
                                         uint32_t b0, uint32_t b1) {
    asm volatile(
        "mma.sync.aligned.m16n8k8.row.col.f32.tf32.tf32.f32 "
        "{%0,%1,%2,%3},{%4,%5,%6,%7},{%8,%9},{%0,%1,%2,%3};"
        : "+f"(d0), "+f"(d1), "+f"(d2), "+f"(d3)
        : "r"(a0), "r"(a1), "r"(a2), "r"(a3), "r"(b0), "r"(b1));
}

__device__ __forceinline__ void cp16(uint32_t dst, const void* src) {
    asm volatile("cp.async.cg.shared.global [%0], [%1], 16;" :: "r"(dst), "l"(src));
}
__device__ __forceinline__ void cp_commit() {
    asm volatile("cp.async.commit_group;");
}
__device__ __forceinline__ void cp_wait0() {
    asm volatile("cp.async.wait_group 0;");
}

// ---------------------------------------------------------------------------
// Kernel 2/4: tf32 tensor-core GEMM  C[M,N] = A[M,K] * B[N,K]^T
// Now __launch_bounds__(256,2) -> regs<=128 -> 2 CTAs/SM.
// mode 0 epilogue rounds K/V to tf32 (so attention can cp.async raw bits).
// ---------------------------------------------------------------------------
#define GSTR 136

__global__ __launch_bounds__(256, 2)
void gemm_tf32(const float* __restrict__ Ain,
               const float* __restrict__ Bw,
               float* __restrict__ Cout,
               const float* __restrict__ cbias,
               int mode) {
    const float* A = (mode == 1) ? g_o : Ain;

    __shared__ float As[2][16][GSTR];
    __shared__ float Bs[2][16][GSTR];

    const int tid  = threadIdx.x;
    const int warp = tid >> 5;
    const int lane = tid & 31;
    const int qr   = lane >> 2;   // 0..7
    const int qk   = lane & 3;    // 0..3
    const int warpM = (warp & 1) * 64;
    const int warpN = (warp >> 1) * 32;

    const int rowBase = blockIdx.y * 128;
    const int colBase = blockIdx.x * 128;

    const int m0 = tid >> 2;
    const int kq = tid & 3;
    const float* a0p = A  + (size_t)(rowBase + m0) * CDIM + kq * 4;
    const float* a1p = a0p + (size_t)64 * CDIM;
    const float* b0p = Bw + (size_t)(colBase + m0) * CDIM + kq * 4;
    const float* b1p = b0p + (size_t)64 * CDIM;
    const int swS = kq << 3;

    float acc[4][4][4];
#pragma unroll
    for (int mt = 0; mt < 4; mt++)
#pragma unroll
        for (int nt = 0; nt < 4; nt++)
#pragma unroll
            for (int r = 0; r < 4; r++) acc[mt][nt][r] = 0.f;

    float4 ra0, ra1, rb0, rb1;

    ra0 = *(const float4*)(a0p); ra1 = *(const float4*)(a1p);
    rb0 = *(const float4*)(b0p); rb1 = *(const float4*)(b1p);
    {
        float av0[4] = {ra0.x, ra0.y, ra0.z, ra0.w};
        float av1[4] = {ra1.x, ra1.y, ra1.z, ra1.w};
        float bv0[4] = {rb0.x, rb0.y, rb0.z, rb0.w};
        float bv1[4] = {rb1.x, rb1.y, rb1.z, rb1.w};
#pragma unroll
        for (int j = 0; j < 4; j++) {
            As[0][kq * 4 + j][m0 ^ swS]        = to_tf32(av0[j]);
            As[0][kq * 4 + j][(m0 + 64) ^ swS] = to_tf32(av1[j]);
            Bs[0][kq * 4 + j][m0 ^ swS]        = to_tf32(bv0[j]);
            Bs[0][kq * 4 + j][(m0 + 64) ^ swS] = to_tf32(bv1[j]);
        }
    }
    __syncthreads();

    for (int it = 0; it < 32; ++it) {
        const int buf = it & 1;
        if (it < 31) {
            const int off = (it + 1) * 16;
            ra0 = *(const float4*)(a0p + off); ra1 = *(const float4*)(a1p + off);
            rb0 = *(const float4*)(b0p + off); rb1 = *(const float4*)(b1p + off);
        }

#pragma unroll
        for (int ks = 0; ks < 16; ks += 8) {
            uint32_t af[4][4], bf[4][2];
            const int kA = ks + qk;
            const int kB = ks + qk + 4;
            const int sA = ((kA >> 2) << 3);
            const int sB = ((kB >> 2) << 3);
#pragma unroll
            for (int mt = 0; mt < 4; mt++) {
                const int m = warpM + mt * 16 + qr;
                af[mt][0] = __float_as_uint(As[buf][kA][m ^ sA]);
                af[mt][1] = __float_as_uint(As[buf][kA][(m + 8) ^ sA]);
                af[mt][2] = __float_as_uint(As[buf][kB][m ^ sB]);
                af[mt][3] = __float_as_uint(As[buf][kB][(m + 8) ^ sB]);
            }
#pragma unroll
            for (int nt = 0; nt < 4; nt++) {
                const int nn = warpN + nt * 8 + qr;
                bf[nt][0] = __float_as_uint(Bs[buf][kA][nn ^ sA]);
                bf[nt][1] = __float_as_uint(Bs[buf][kB][nn ^ sB]);
            }
#pragma unroll
            for (int mt = 0; mt < 4; mt++)
#pragma unroll
                for (int nt = 0; nt < 4; nt++)
                    mma_tf32(acc[mt][nt][0], acc[mt][nt][1], acc[mt][nt][2], acc[mt][nt][3],
                             af[mt][0], af[mt][1], af[mt][2], af[mt][3],
                             bf[nt][0], bf[nt][1]);
        }

        if (it < 31) {
            const int nbuf = buf ^ 1;
            float av0[4] = {ra0.x, ra0.y, ra0.z, ra0.w};
            float av1[4] = {ra1.x, ra1.y, ra1.z, ra1.w};
            float bv0[4] = {rb0.x, rb0.y, rb0.z, rb0.w};
            float bv1[4] = {rb1.x, rb1.y, rb1.z, rb1.w};
#pragma unroll
            for (int j = 0; j < 4; j++) {
                As[nbuf][kq * 4 + j][m0 ^ swS]        = to_tf32(av0[j]);
                As[nbuf][kq * 4 + j][(m0 + 64) ^ swS] = to_tf32(av1[j]);
                Bs[nbuf][kq * 4 + j][m0 ^ swS]        = to_tf32(bv0[j]);
                Bs[nbuf][kq * 4 + j][(m0 + 64) ^ swS] = to_tf32(bv1[j]);
            }
        }
        __syncthreads();
    }

    if (mode == 0) {
        // K/V scatter, tf32-rounded so the attention kernel can copy raw bits
#pragma unroll
        for (int mt = 0; mt < 4; mt++) {
            const int row = rowBase + warpM + mt * 16 + qr;
            const int bb0 = row / NTOK;
            const int nn0 = row - bb0 * NTOK;
            const int bb8 = (row + 8) / NTOK;
            const int nn8 = (row + 8) - bb8 * NTOK;
#pragma unroll
            for (int nt = 0; nt < 4; nt++) {
                const int col = colBase + warpN + nt * 8 + qk * 2;
                const int hv  = (col >> 5) & 15;
                const int d   = col & 31;
                float* dst = (col < 512) ? g_k : g_v;
                size_t off0 = ((((size_t)bb0 * NH + hv) * NTOK) + nn0) * HD + d;
                size_t off8 = ((((size_t)bb8 * NH + hv) * NTOK) + nn8) * HD + d;
                *(float2*)(dst + off0) =
                    make_float2(to_tf32(acc[mt][nt][0]), to_tf32(acc[mt][nt][1]));
                *(float2*)(dst + off8) =
                    make_float2(to_tf32(acc[mt][nt][2]), to_tf32(acc[mt][nt][3]));
            }
        }
    } else {
#pragma unroll
        for (int mt = 0; mt < 4; mt++) {
            const int row = rowBase + warpM + mt * 16 + qr;
#pragma unroll
            for (int nt = 0; nt < 4; nt++) {
                const int col = colBase + warpN + nt * 8 + qk * 2;
                const float b0v = cbias[col], b1v = cbias[col + 1];
                *(float2*)(Cout + (size_t)row * CDIM + col) =
                    make_float2(acc[mt][nt][0] + b0v, acc[mt][nt][1] + b1v);
                *(float2*)(Cout + (size_t)(row + 8) * CDIM + col) =
                    make_float2(acc[mt][nt][2] + b0v, acc[mt][nt][3] + b1v);
            }
        }
    }
}

// ---------------------------------------------------------------------------
// Kernel 3: tensor-core flash attention, cp.async double-buffered.
// grid (b*h = 2048, 3 query tiles of 128), block 256 (8 warps).
// K/V staged async in 64-key chunks (2 buffers); each chunk processed as two
// 32-key subchunks (sacc = 16 regs -> fits 3 CTAs/SM via launch_bounds).
// smem: K 2*[64][36] + V 2*[64][36] + P 8*[16][36] = 55296 B
// ---------------------------------------------------------------------------
#define KSTR 36
#define PSTR 36
#define ATT_SMEM ((4 * 64 * KSTR + 8 * 16 * PSTR) * 4)

__global__ __launch_bounds__(256, 3)
void attn_mma(const float* __restrict__ qg) {
    const int bh = blockIdx.x;
    const int bb = bh >> 4, h = bh & 15;
    const int Bi = bb >> 6, wi = bb & 63;
    const int qbase = blockIdx.y * 128;
    const int tid = threadIdx.x, warp = tid >> 5, lane = tid & 31;
    const int g = lane >> 2, t = lane & 3;

    extern __shared__ float sm[];
    float* KsA[2] = {sm, sm + 64 * KSTR};
    float* VsA[2] = {sm + 2 * 64 * KSTR, sm + 3 * 64 * KSTR};
    float* Ps = sm + 4 * 64 * KSTR + warp * (16 * PSTR);

    const int r0 = qbase + warp * 16 + g;
    const int r1 = r0 + 8;
    const int r0c = min(r0, NTOK - 1), r1c = min(r1, NTOK - 1);

    // Q fragments (registers, pre-scaled)
    {
    }
    const float* q0p = qg + (((size_t)Bi * NH + h) * NTOK + r0c) * HD;
    const float* q1p = qg + (((size_t)Bi * NH + h) * NTOK + r1c) * HD;
    uint32_t qa[4][4];
#pragma unroll
    for (int ks = 0; ks < 4; ks++) {
        qa[ks][0] = __float_as_uint(to_tf32(q0p[ks * 8 + t] * SCALE_F));
        qa[ks][1] = __float_as_uint(to_tf32(q1p[ks * 8 + t] * SCALE_F));
        qa[ks][2] = __float_as_uint(to_tf32(q0p[ks * 8 + t + 4] * SCALE_F));
        qa[ks][3] = __float_as_uint(to_tf32(q1p[ks * 8 + t + 4] * SCALE_F));
    }

    const float* brow0 = g_bias  + ((size_t)h  * NTOK + r0c) * BMSTR;
    const float* brow1 = g_bias  + ((size_t)h  * NTOK + r1c) * BMSTR;
    const float* mrow0 = g_maskp + ((size_t)wi * NTOK + r0c) * BMSTR;
    const float* mrow1 = g_maskp + ((size_t)wi * NTOK + r1c) * BMSTR;

    const float* kb = g_k + ((size_t)bb * NH + h) * NTOK * HD;
    const float* vb = g_v + ((size_t)bb * NH + h) * NTOK * HD;

    // staging assignment: 8 consecutive floats per thread
    const int ln = tid >> 2;          // 0..63 (key row)
    const int lp = (tid & 3) * 8;     // float offset within row

    const uint32_t ksm[2] = {(uint32_t)__cvta_generic_to_shared(KsA[0] + ln * KSTR + lp),
                             (uint32_t)__cvta_generic_to_shared(KsA[1] + ln * KSTR + lp)};
    const uint32_t vsm[2] = {(uint32_t)__cvta_generic_to_shared(VsA[0] + ln * KSTR + lp),
                             (uint32_t)__cvta_generic_to_shared(VsA[1] + ln * KSTR + lp)};

    float rm0 = -1e30f, rm1 = -1e30f, l0 = 0.f, l1 = 0.f;
    float oacc[4][4];
#pragma unroll
    for (int df = 0; df < 4; df++)
#pragma unroll
        for (int r = 0; r < 4; r++) oacc[df][r] = 0.f;

    // prologue: stage chunk 0 into buffer 0
    {
        int gn = min(ln, NTOK - 1);
        const float* ksrc = kb + (size_t)gn * HD + lp;
        const float* vsrc = vb + (size_t)gn * HD + lp;
        cp16(ksm[0], ksrc);     cp16(ksm[0] + 16, ksrc + 4);
        cp16(vsm[0], vsrc);     cp16(vsm[0] + 16, vsrc + 4);
        cp_commit();
    }
    cp_wait0();
    __syncthreads();

    for (int c = 0; c < 6; c++) {
        const int buf = c & 1;
        if (c < 5) {
            int gn = min((c + 1) * 64 + ln, NTOK - 1);
            const float* ksrc = kb + (size_t)gn * HD + lp;
            const float* vsrc = vb + (size_t)gn * HD + lp;
            const int nb = buf ^ 1;
            cp16(ksm[nb], ksrc);     cp16(ksm[nb] + 16, ksrc + 4);
            cp16(vsm[nb], vsrc);     cp16(vsm[nb] + 16, vsrc + 4);
            cp_commit();
        }
        const float* Ks = KsA[buf];
        const float* Vs = VsA[buf];

#pragma unroll
        for (int h32 = 0; h32 < 2; h32++) {
            const int kb0 = c * 64 + h32 * 32;
            const int nrow0 = h32 * 32;

            // S = Q K^T : 4 n-frags x 4 k-steps
            float sacc[4][4];
#pragma unroll
            for (int nf = 0; nf < 4; nf++)
#pragma unroll
                for (int r = 0; r < 4; r++) sacc[nf][r] = 0.f;
#pragma unroll
            for (int ks = 0; ks < 4; ks++) {
#pragma unroll
                for (int nf = 0; nf < 4; nf++) {
                    uint32_t b0 = __float_as_uint(Ks[(nrow0 + nf * 8 + g) * KSTR + ks * 8 + t]);
                    uint32_t b1 = __float_as_uint(Ks[(nrow0 + nf * 8 + g) * KSTR + ks * 8 + t + 4]);
                    mma_tf32(sacc[nf][0], sacc[nf][1], sacc[nf][2], sacc[nf][3],
                             qa[ks][0], qa[ks][1], qa[ks][2], qa[ks][3], b0, b1);
                }
            }

            // + bias + mask, OOB -> -inf, subchunk row max
            float cm0 = -1e30f, cm1 = -1e30f;
#pragma unroll
            for (int nf = 0; nf < 4; nf++) {
                int col = kb0 + nf * 8 + 2 * t;
                float2 bv0 = *(const float2*)(brow0 + col);
                float2 mv0 = *(const float2*)(mrow0 + col);
                float2 bv1 = *(const float2*)(brow1 + col);
                float2 mv1 = *(const float2*)(mrow1 + col);
                sacc[nf][0] = (col     < NTOK) ? sacc[nf][0] + bv0.x + mv0.x : -1e30f;
                sacc[nf][1] = (col + 1 < NTOK) ? sacc[nf][1] + bv0.y + mv0.y : -1e30f;
                sacc[nf][2] = (col     < NTOK) ? sacc[nf][2] + bv1.x + mv1.x : -1e30f;
                sacc[nf][3] = (col + 1 < NTOK) ? sacc[nf][3] + bv1.y + mv1.y : -1e30f;
                cm0 = fmaxf(cm0, fmaxf(sacc[nf][0], sacc[nf][1]));
                cm1 = fmaxf(cm1, fmaxf(sacc[nf][2], sacc[nf][3]));
            }
            cm0 = fmaxf(cm0, __shfl_xor_sync(0xffffffffu, cm0, 1));
            cm0 = fmaxf(cm0, __shfl_xor_sync(0xffffffffu, cm0, 2));
            cm1 = fmaxf(cm1, __shfl_xor_sync(0xffffffffu, cm1, 1));
            cm1 = fmaxf(cm1, __shfl_xor_sync(0xffffffffu, cm1, 2));

            float mn0 = fmaxf(rm0, cm0), mn1 = fmaxf(rm1, cm1);
            float sc0 = __expf(rm0 - mn0), sc1 = __expf(rm1 - mn1);
            rm0 = mn0; rm1 = mn1;

            float ls0 = 0.f, ls1 = 0.f;
#pragma unroll
            for (int nf = 0; nf < 4; nf++) {
                float p0 = __expf(sacc[nf][0] - mn0);
                float p1 = __expf(sacc[nf][1] - mn0);
                float p2 = __expf(sacc[nf][2] - mn1);
                float p3 = __expf(sacc[nf][3] - mn1);
                ls0 += p0 + p1; ls1 += p2 + p3;
                *(float2*)(Ps + g * PSTR       + nf * 8 + 2 * t) = make_float2(to_tf32(p0), to_tf32(p1));
                *(float2*)(Ps + (g + 8) * PSTR + nf * 8 + 2 * t) = make_float2(to_tf32(p2), to_tf32(p3));
            }
            ls0 += __shfl_xor_sync(0xffffffffu, ls0, 1);
            ls0 += __shfl_xor_sync(0xffffffffu, ls0, 2);
            ls1 += __shfl_xor_sync(0xffffffffu, ls1, 1);
            ls1 += __shfl_xor_sync(0xffffffffu, ls1, 2);
            l0 = l0 * sc0 + ls0;
            l1 = l1 * sc1 + ls1;

#pragma unroll
            for (int df = 0; df < 4; df++) {
                oacc[df][0] *= sc0; oacc[df][1] *= sc0;
                oacc[df][2] *= sc1; oacc[df][3] *= sc1;
            }
            __syncwarp();

            // O += P V : 4 k-steps x 4 d-frags (32 keys)
#pragma unroll
            for (int ks = 0; ks < 4; ks++) {
                uint32_t a0 = __float_as_uint(Ps[g * PSTR       + ks * 8 + t]);
                uint32_t a1 = __float_as_uint(Ps[(g + 8) * PSTR + ks * 8 + t]);
                uint32_t a2 = __float_as_uint(Ps[g * PSTR       + ks * 8 + t + 4]);
                uint32_t a3 = __float_as_uint(Ps[(g + 8) * PSTR + ks * 8 + t + 4]);
#pragma unroll
                for (int df = 0; df < 4; df++) {
                    uint32_t b0 = __float_as_uint(Vs[(nrow0 + ks * 8 + t) * KSTR + df * 8 + g]);
                    uint32_t b1 = __float_as_uint(Vs[(nrow0 + ks * 8 + t + 4) * KSTR + df * 8 + g]);
                    mma_tf32(oacc[df][0], oacc[df][1], oacc[df][2], oacc[df][3],
                             a0, a1, a2, a3, b0, b1);
                }
            }
            __syncwarp();
        }

        if (c < 5) cp_wait0();
        __syncthreads();
    }

    // epilogue: normalize + store
    float inv0 = 1.f / l0, inv1 = 1.f / l1;
    if (r0 < NTOK) {
        float* orow = g_o + ((size_t)bb * NTOK + r0) * CDIM + h * HD;
#pragma unroll
        for (int df = 0; df < 4; df++)
            *(float2*)(orow + df * 8 + 2 * t) =
                make_float2(oacc[df][0] * inv0, oacc[df][1] * inv0);
    }
    if (r1 < NTOK) {
        float* orow = g_o + ((size_t)bb * NTOK + r1) * CDIM + h * HD;
#pragma unroll
        for (int df = 0; df < 4; df++)
            *(float2*)(orow + df * 8 + 2 * t) =
                make_float2(oacc[df][2] * inv1, oacc[df][3] * inv1);
    }
}

// ---------------------------------------------------------------------------
// Launch
// ---------------------------------------------------------------------------
extern "C" void kernel_launch(void* const* d_in, const int* in_sizes, int n_in,
                              void* d_out, int out_size) {
    const float* x      = (const float*)d_in[0];
    // d_in[1..3] = D,H,W scalars (constant 7) — unused
    const float* mask   = (const float*)d_in[4];
    const float* qg     = (const float*)d_in[5];
    const float* kv_w   = (const float*)d_in[6];
    const float* proj_w = (const float*)d_in[7];
    const float* proj_b = (const float*)d_in[8];
    const float* rpb    = (const float*)d_in[9];
    float* out = (float*)d_out;

    cudaFuncSetAttribute(attn_mma, cudaFuncAttributeMaxDynamicSharedMemorySize, ATT_SMEM);

    // 1) padded bias + mask tables
    bias_kernel<<<(NTOK * BMSTR + 255) / 256, 256>>>(rpb);
    mask_copy_kernel<<<(64 * NTOK * BMSTR + 255) / 256, 256>>>(mask);

    // 2) KV projection: [43904,512] x [1024,512]^T -> scatter g_k/g_v (tf32 MMA)
    gemm_tf32<<<dim3(1024 / 128, MROWS / 128), 256>>>(x, kv_w, nullptr, nullptr, 0);

    // 3) tensor-core flash attention -> g_o
    attn_mma<<<dim3(NB * NH, 3), 256, ATT_SMEM>>>(qg);

    // 4) output projection: [43904,512] x [512,512]^T + bias -> d_out (tf32 MMA)
    gemm_tf32<<<dim3(CDIM / 128, MROWS / 128), 256>>>(nullptr, proj_w, out, proj_b, 1);
}

// round 12
// speedup vs baseline: 2.9903x; 1.0434x over previous
#include <cuda_runtime.h>
#include <cstdint>

// ---------------------------------------------------------------------------
// Problem constants
// ---------------------------------------------------------------------------
#define NB     128          // b = B*nw
#define NTOK   343          // n
#define CDIM   512          // c
#define NH     16           // heads
#define HD     32           // head dim
#define MROWS  (NB * NTOK)  // 43904 = 343 * 128
#define SCALE_F 0.17677669529663687f   // 32^-0.5
#define BMSTR  352          // padded bias/mask row stride
#define VTSTR  384          // padded V^T row stride (keys), 16B-aligned rows

// ---------------------------------------------------------------------------
// Scratch (device globals; no allocations allowed)
// ---------------------------------------------------------------------------
__device__ float g_k[(size_t)NB * NH * NTOK * HD];        // [b][h][n][32] d-permuted, tf32
__device__ float g_vT[(size_t)NB * NH * HD * VTSTR];      // [b][h][d][n] transposed, tf32
__device__ float g_bias[(size_t)NH * NTOK * BMSTR];       // [h][i][j] stride 352
__device__ float g_maskp[(size_t)64 * NTOK * BMSTR];      // [wi][i][j] stride 352
__device__ float g_o[(size_t)MROWS * CDIM];               // [b*n][c] head-major cols

// ---------------------------------------------------------------------------
// Kernel 1a: relative position bias  bias[h][i][j] = rpb[rel(i,j)*16 + h]
// ---------------------------------------------------------------------------
__global__ void bias_kernel(const float* __restrict__ rpb) {
    int idx = blockIdx.x * 256 + threadIdx.x;
    if (idx >= NTOK * BMSTR) return;
    int i = idx / BMSTR, j = idx % BMSTR;
    if (j >= NTOK) {
#pragma unroll
        for (int h = 0; h < NH; h++)
            g_bias[(size_t)h * NTOK * BMSTR + idx] = 0.f;
        return;
    }
    int di = i / 49, hi = (i / 7) % 7, wi = i % 7;
    int dj = j / 49, hj = (j / 7) % 7, wj = j % 7;
    int rel = (di - dj + 6) * 169 + (hi - hj + 6) * 13 + (wi - wj + 6);
    const float* src = rpb + rel * NH;
#pragma unroll
    for (int h = 0; h < NH; h++)
        g_bias[(size_t)h * NTOK * BMSTR + idx] = src[h];
}

// ---------------------------------------------------------------------------
// Kernel 1b: repack mask into padded stride-352 table
// ---------------------------------------------------------------------------
__global__ void mask_copy_kernel(const float* __restrict__ mask) {
    int idx = blockIdx.x * 256 + threadIdx.x;
    if (idx >= 64 * NTOK * BMSTR) return;
    int w = idx / (NTOK * BMSTR);
    int r = idx % (NTOK * BMSTR);
    int i = r / BMSTR, j = r % BMSTR;
    g_maskp[idx] = (j < NTOK) ? mask[((size_t)w * NTOK + i) * NTOK + j] : 0.f;
}

// ---------------------------------------------------------------------------
// tf32 / cp.async helpers
// ---------------------------------------------------------------------------
__device__ __forceinline__ float to_tf32(float x) {
    asm("cvt.rna.tf32.f32 %0, %0;" : "+f"(x));
    return x;
}

__device__ __forceinline__ void mma_tf32(float& d0, float& d1, float& d2, float& d3,
                                         uint32_t a0, uint32_t a1, uint32_t a2, uint32_t a3,
                                         uint32_t b0, uint32_t b1) {
    asm volatile(
        "mma.sync.aligned.m16n8k8.row.col.f32.tf32.tf32.f32 "
        "{%0,%1,%2,%3},{%4,%5,%6,%7},{%8,%9},{%0,%1,%2,%3};"
        : "+f"(d0), "+f"(d1), "+f"(d2), "+f"(d3)
        : "r"(a0), "r"(a1), "r"(a2), "r"(a3), "r"(b0), "r"(b1));
}

__device__ __forceinline__ void cp16(uint32_t dst, const void* src) {
    asm volatile("cp.async.cg.shared.global [%0], [%1], 16;" :: "r"(dst), "l"(src));
}
__device__ __forceinline__ void cp_commit() {
    asm volatile("cp.async.commit_group;");
}
__device__ __forceinline__ void cp_wait0() {
    asm volatile("cp.async.wait_group 0;");
}

// within-8-group column permutation so B-frag pairs (t, t+4) sit adjacent
__device__ __forceinline__ int dperm(int d) {
    return (d & 24) | ((d & 3) << 1) | ((d >> 2) & 1);
}

// ---------------------------------------------------------------------------
// Kernel 2/4: tf32 tensor-core GEMM  C[M,N] = A[M,K] * B[N,K]^T
// mode 0 epilogue: K -> g_k (d-permuted), V -> g_vT (transposed), tf32-rounded
// mode 1 epilogue: Cout = acc + cbias, A = g_o
// ---------------------------------------------------------------------------
#define GSTR 136

__global__ __launch_bounds__(256, 2)
void gemm_tf32(const float* __restrict__ Ain,
               const float* __restrict__ Bw,
               float* __restrict__ Cout,
               const float* __restrict__ cbias,
               int mode) {
    const float* A = (mode == 1) ? g_o : Ain;

    __shared__ float As[2][16][GSTR];
    __shared__ float Bs[2][16][GSTR];

    const int tid  = threadIdx.x;
    const int warp = tid >> 5;
    const int lane = tid & 31;
    const int qr   = lane >> 2;   // 0..7
    const int qk   = lane & 3;    // 0..3
    const int warpM = (warp & 1) * 64;
    const int warpN = (warp >> 1) * 32;

    const int rowBase = blockIdx.y * 128;
    const int colBase = blockIdx.x * 128;

    const int m0 = tid >> 2;
    const int kq = tid & 3;
    const float* a0p = A  + (size_t)(rowBase + m0) * CDIM + kq * 4;
    const float* a1p = a0p + (size_t)64 * CDIM;
    const float* b0p = Bw + (size_t)(colBase + m0) * CDIM + kq * 4;
    const float* b1p = b0p + (size_t)64 * CDIM;
    const int swS = kq << 3;

    float acc[4][4][4];
#pragma unroll
    for (int mt = 0; mt < 4; mt++)
#pragma unroll
        for (int nt = 0; nt < 4; nt++)
#pragma unroll
            for (int r = 0; r < 4; r++) acc[mt][nt][r] = 0.f;

    float4 ra0, ra1, rb0, rb1;

    ra0 = *(const float4*)(a0p); ra1 = *(const float4*)(a1p);
    rb0 = *(const float4*)(b0p); rb1 = *(const float4*)(b1p);
    {
        float av0[4] = {ra0.x, ra0.y, ra0.z, ra0.w};
        float av1[4] = {ra1.x, ra1.y, ra1.z, ra1.w};
        float bv0[4] = {rb0.x, rb0.y, rb0.z, rb0.w};
        float bv1[4] = {rb1.x, rb1.y, rb1.z, rb1.w};
#pragma unroll
        for (int j = 0; j < 4; j++) {
            As[0][kq * 4 + j][m0 ^ swS]        = to_tf32(av0[j]);
            As[0][kq * 4 + j][(m0 + 64) ^ swS] = to_tf32(av1[j]);
            Bs[0][kq * 4 + j][m0 ^ swS]        = to_tf32(bv0[j]);
            Bs[0][kq * 4 + j][(m0 + 64) ^ swS] = to_tf32(bv1[j]);
        }
    }
    __syncthreads();

    for (int it = 0; it < 32; ++it) {
        const int buf = it & 1;
        if (it < 31) {
            const int off = (it + 1) * 16;
            ra0 = *(const float4*)(a0p + off); ra1 = *(const float4*)(a1p + off);
            rb0 = *(const float4*)(b0p + off); rb1 = *(const float4*)(b1p + off);
        }

#pragma unroll
        for (int ks = 0; ks < 16; ks += 8) {
            uint32_t af[4][4], bf[4][2];
            const int kA = ks + qk;
            const int kB = ks + qk + 4;
            const int sA = ((kA >> 2) << 3);
            const int sB = ((kB >> 2) << 3);
#pragma unroll
            for (int mt = 0; mt < 4; mt++) {
                const int m = warpM + mt * 16 + qr;
                af[mt][0] = __float_as_uint(As[buf][kA][m ^ sA]);
                af[mt][1] = __float_as_uint(As[buf][kA][(m + 8) ^ sA]);
                af[mt][2] = __float_as_uint(As[buf][kB][m ^ sB]);
                af[mt][3] = __float_as_uint(As[buf][kB][(m + 8) ^ sB]);
            }
#pragma unroll
            for (int nt = 0; nt < 4; nt++) {
                const int nn = warpN + nt * 8 + qr;
                bf[nt][0] = __float_as_uint(Bs[buf][kA][nn ^ sA]);
                bf[nt][1] = __float_as_uint(Bs[buf][kB][nn ^ sB]);
            }
#pragma unroll
            for (int mt = 0; mt < 4; mt++)
#pragma unroll
                for (int nt = 0; nt < 4; nt++)
                    mma_tf32(acc[mt][nt][0], acc[mt][nt][1], acc[mt][nt][2], acc[mt][nt][3],
                             af[mt][0], af[mt][1], af[mt][2], af[mt][3],
                             bf[nt][0], bf[nt][1]);
        }

        if (it < 31) {
            const int nbuf = buf ^ 1;
            float av0[4] = {ra0.x, ra0.y, ra0.z, ra0.w};
            float av1[4] = {ra1.x, ra1.y, ra1.z, ra1.w};
            float bv0[4] = {rb0.x, rb0.y, rb0.z, rb0.w};
            float bv1[4] = {rb1.x, rb1.y, rb1.z, rb1.w};
#pragma unroll
            for (int j = 0; j < 4; j++) {
                As[nbuf][kq * 4 + j][m0 ^ swS]        = to_tf32(av0[j]);
                As[nbuf][kq * 4 + j][(m0 + 64) ^ swS] = to_tf32(av1[j]);
                Bs[nbuf][kq * 4 + j][m0 ^ swS]        = to_tf32(bv0[j]);
                Bs[nbuf][kq * 4 + j][(m0 + 64) ^ swS] = to_tf32(bv1[j]);
            }
        }
        __syncthreads();
    }

    if (mode == 0) {
        // K -> g_k (d-permuted within 8-groups); V -> g_vT (transposed). tf32-rounded.
#pragma unroll
        for (int mt = 0; mt < 4; mt++) {
            const int row = rowBase + warpM + mt * 16 + qr;
            const int bb0 = row / NTOK;
            const int nn0 = row - bb0 * NTOK;
            const int bb8 = (row + 8) / NTOK;
            const int nn8 = (row + 8) - bb8 * NTOK;
#pragma unroll
            for (int nt = 0; nt < 4; nt++) {
                const int col = colBase + warpN + nt * 8 + qk * 2;
                const int d   = col & 31;
                const float v0 = to_tf32(acc[mt][nt][0]);
                const float v1 = to_tf32(acc[mt][nt][1]);
                const float v2 = to_tf32(acc[mt][nt][2]);
                const float v3 = to_tf32(acc[mt][nt][3]);
                if (col < 512) {
                    const int hv = col >> 5;
                    const int d0p = dperm(d), d1p = dperm(d + 1);
                    size_t base0 = ((((size_t)bb0 * NH + hv) * NTOK) + nn0) * HD;
                    size_t base8 = ((((size_t)bb8 * NH + hv) * NTOK) + nn8) * HD;
                    g_k[base0 + d0p] = v0;  g_k[base0 + d1p] = v1;
                    g_k[base8 + d0p] = v2;  g_k[base8 + d1p] = v3;
                } else {
                    const int hv = (col - 512) >> 5;
                    size_t r0v = (((size_t)bb0 * NH + hv) * HD + d) * VTSTR;
                    size_t r1v = (((size_t)bb0 * NH + hv) * HD + d + 1) * VTSTR;
                    size_t r0w = (((size_t)bb8 * NH + hv) * HD + d) * VTSTR;
                    size_t r1w = (((size_t)bb8 * NH + hv) * HD + d + 1) * VTSTR;
                    g_vT[r0v + nn0] = v0;  g_vT[r1v + nn0] = v1;
                    g_vT[r0w + nn8] = v2;  g_vT[r1w + nn8] = v3;
                }
            }
        }
    } else {
#pragma unroll
        for (int mt = 0; mt < 4; mt++) {
            const int row = rowBase + warpM + mt * 16 + qr;
#pragma unroll
            for (int nt = 0; nt < 4; nt++) {
                const int col = colBase + warpN + nt * 8 + qk * 2;
                const float b0v = cbias[col], b1v = cbias[col + 1];
                *(float2*)(Cout + (size_t)row * CDIM + col) =
                    make_float2(acc[mt][nt][0] + b0v, acc[mt][nt][1] + b1v);
                *(float2*)(Cout + (size_t)(row + 8) * CDIM + col) =
                    make_float2(acc[mt][nt][2] + b0v, acc[mt][nt][3] + b1v);
            }
        }
    }
}

// ---------------------------------------------------------------------------
// Kernel 3: tensor-core flash attention, cp.async double-buffered.
// grid (b*h = 2048, 3 query tiles of 128), block 256 (8 warps, 16 q/warp).
// P never touches smem: S C-frags feed PV A-frags directly (V in natural
// key order, transposed layout); K/V B-frags are single float2 LDS.
// smem: K 2*[64][40] + V^T 2*[32][72] = 38912 B
// ---------------------------------------------------------------------------
#define KSTR 40
#define VSTR 72
#define ATT_SMEM ((2 * 64 * KSTR + 2 * 32 * VSTR) * 4)

__global__ __launch_bounds__(256, 3)
void attn_mma(const float* __restrict__ qg) {
    const int bh = blockIdx.x;
    const int bb = bh >> 4, h = bh & 15;
    const int Bi = bb >> 6, wi = bb & 63;
    const int qbase = blockIdx.y * 128;
    const int tid = threadIdx.x, warp = tid >> 5, lane = tid & 31;
    const int g = lane >> 2, t = lane & 3;

    extern __shared__ float sm[];
    float* KsA[2] = {sm, sm + 64 * KSTR};
    float* VsA[2] = {sm + 2 * 64 * KSTR, sm + 2 * 64 * KSTR + 32 * VSTR};

    const int r0 = qbase + warp * 16 + g;
    const int r1 = r0 + 8;
    const int r0c = min(r0, NTOK - 1), r1c = min(r1, NTOK - 1);

    // Q fragments (registers, pre-scaled). Natural d order (K permutation
    // was chosen so Q fragment indexing is unchanged).
    const float* q0p = qg + (((size_t)Bi * NH + h) * NTOK + r0c) * HD;
    const float* q1p = qg + (((size_t)Bi * NH + h) * NTOK + r1c) * HD;
    uint32_t qa[4][4];
#pragma unroll
    for (int ks = 0; ks < 4; ks++) {
        qa[ks][0] = __float_as_uint(to_tf32(q0p[ks * 8 + t] * SCALE_F));
        qa[ks][1] = __float_as_uint(to_tf32(q1p[ks * 8 + t] * SCALE_F));
        qa[ks][2] = __float_as_uint(to_tf32(q0p[ks * 8 + t + 4] * SCALE_F));
        qa[ks][3] = __float_as_uint(to_tf32(q1p[ks * 8 + t + 4] * SCALE_F));
    }

    const float* brow0 = g_bias  + ((size_t)h  * NTOK + r0c) * BMSTR;
    const float* brow1 = g_bias  + ((size_t)h  * NTOK + r1c) * BMSTR;
    const float* mrow0 = g_maskp + ((size_t)wi * NTOK + r0c) * BMSTR;
    const float* mrow1 = g_maskp + ((size_t)wi * NTOK + r1c) * BMSTR;

    const float* kb  = g_k  + ((size_t)bb * NH + h) * NTOK * HD;
    const float* vtb = g_vT + ((size_t)bb * NH + h) * HD * VTSTR;

    // staging: K = 64 rows x 32 floats; V^T = 32 rows x 64 floats
    const int kln = tid >> 2, klp = (tid & 3) * 8;
    const int vrow = tid >> 3, vseg = (tid & 7) * 8;

    const uint32_t ksm[2] = {(uint32_t)__cvta_generic_to_shared(KsA[0] + kln * KSTR + klp),
                             (uint32_t)__cvta_generic_to_shared(KsA[1] + kln * KSTR + klp)};
    const uint32_t vsm[2] = {(uint32_t)__cvta_generic_to_shared(VsA[0] + vrow * VSTR + vseg),
                             (uint32_t)__cvta_generic_to_shared(VsA[1] + vrow * VSTR + vseg)};

    float rm0 = -1e30f, rm1 = -1e30f, l0 = 0.f, l1 = 0.f;
    float oacc[4][4];
#pragma unroll
    for (int df = 0; df < 4; df++)
#pragma unroll
        for (int r = 0; r < 4; r++) oacc[df][r] = 0.f;

    // prologue: stage chunk 0 into buffer 0
    {
        int gn = min(kln, NTOK - 1);
        const float* ksrc = kb + (size_t)gn * HD + klp;
        const float* vsrc = vtb + (size_t)vrow * VTSTR + vseg;
        cp16(ksm[0], ksrc);     cp16(ksm[0] + 16, ksrc + 4);
        cp16(vsm[0], vsrc);     cp16(vsm[0] + 16, vsrc + 4);
        cp_commit();
    }
    cp_wait0();
    __syncthreads();

    for (int c = 0; c < 6; c++) {
        const int buf = c & 1;
        if (c < 5) {
            int gn = min((c + 1) * 64 + kln, NTOK - 1);
            const float* ksrc = kb + (size_t)gn * HD + klp;
            const float* vsrc = vtb + (size_t)vrow * VTSTR + (c + 1) * 64 + vseg;
            const int nb = buf ^ 1;
            cp16(ksm[nb], ksrc);     cp16(ksm[nb] + 16, ksrc + 4);
            cp16(vsm[nb], vsrc);     cp16(vsm[nb] + 16, vsrc + 4);
            cp_commit();
        }
        const float* Ks = KsA[buf];
        const float* Vs = VsA[buf];

#pragma unroll
        for (int h32 = 0; h32 < 2; h32++) {
            const int kb0 = c * 64 + h32 * 32;
            const int nrow0 = h32 * 32;

            // S = Q K^T : 4 n-frags x 4 k-steps; B-frag = one float2 LDS
            float sacc[4][4];
#pragma unroll
            for (int nf = 0; nf < 4; nf++)
#pragma unroll
                for (int r = 0; r < 4; r++) sacc[nf][r] = 0.f;
#pragma unroll
            for (int ks = 0; ks < 4; ks++) {
#pragma unroll
                for (int nf = 0; nf < 4; nf++) {
                    float2 bp = *(const float2*)&Ks[(nrow0 + nf * 8 + g) * KSTR + ks * 8 + 2 * t];
                    mma_tf32(sacc[nf][0], sacc[nf][1], sacc[nf][2], sacc[nf][3],
                             qa[ks][0], qa[ks][1], qa[ks][2], qa[ks][3],
                             __float_as_uint(bp.x), __float_as_uint(bp.y));
                }
            }

            // + bias + mask, OOB -> -inf, subchunk row max
            float cm0 = -1e30f, cm1 = -1e30f;
#pragma unroll
            for (int nf = 0; nf < 4; nf++) {
                int col = kb0 + nf * 8 + 2 * t;
                float2 bv0 = *(const float2*)(brow0 + col);
                float2 mv0 = *(const float2*)(mrow0 + col);
                float2 bv1 = *(const float2*)(brow1 + col);
                float2 mv1 = *(const float2*)(mrow1 + col);
                sacc[nf][0] = (col     < NTOK) ? sacc[nf][0] + bv0.x + mv0.x : -1e30f;
                sacc[nf][1] = (col + 1 < NTOK) ? sacc[nf][1] + bv0.y + mv0.y : -1e30f;
                sacc[nf][2] = (col     < NTOK) ? sacc[nf][2] + bv1.x + mv1.x : -1e30f;
                sacc[nf][3] = (col + 1 < NTOK) ? sacc[nf][3] + bv1.y + mv1.y : -1e30f;
                cm0 = fmaxf(cm0, fmaxf(sacc[nf][0], sacc[nf][1]));
                cm1 = fmaxf(cm1, fmaxf(sacc[nf][2], sacc[nf][3]));
            }
            cm0 = fmaxf(cm0, __shfl_xor_sync(0xffffffffu, cm0, 1));
            cm0 = fmaxf(cm0, __shfl_xor_sync(0xffffffffu, cm0, 2));
            cm1 = fmaxf(cm1, __shfl_xor_sync(0xffffffffu, cm1, 1));
            cm1 = fmaxf(cm1, __shfl_xor_sync(0xffffffffu, cm1, 2));

            float mn0 = fmaxf(rm0, cm0), mn1 = fmaxf(rm1, cm1);
            float sc0 = __expf(rm0 - mn0), sc1 = __expf(rm1 - mn1);
            rm0 = mn0; rm1 = mn1;

            // exp in-place; P stays in registers as PV A-fragments
            float ls0 = 0.f, ls1 = 0.f;
#pragma unroll
            for (int nf = 0; nf < 4; nf++) {
                float p0 = __expf(sacc[nf][0] - mn0);
                float p1 = __expf(sacc[nf][1] - mn0);
                float p2 = __expf(sacc[nf][2] - mn1);
                float p3 = __expf(sacc[nf][3] - mn1);
                ls0 += p0 + p1; ls1 += p2 + p3;
                sacc[nf][0] = to_tf32(p0);
                sacc[nf][1] = to_tf32(p1);
                sacc[nf][2] = to_tf32(p2);
                sacc[nf][3] = to_tf32(p3);
            }
            ls0 += __shfl_xor_sync(0xffffffffu, ls0, 1);
            ls0 += __shfl_xor_sync(0xffffffffu, ls0, 2);
            ls1 += __shfl_xor_sync(0xffffffffu, ls1, 1);
            ls1 += __shfl_xor_sync(0xffffffffu, ls1, 2);
            l0 = l0 * sc0 + ls0;
            l1 = l1 * sc1 + ls1;

#pragma unroll
            for (int df = 0; df < 4; df++) {
                oacc[df][0] *= sc0; oacc[df][1] *= sc0;
                oacc[df][2] *= sc1; oacc[df][3] *= sc1;
            }

            // O += P V : A-frags direct from sacc regs; B-frag = one float2 LDS
            // a0 = P[g][key 2t]   = sacc[ks][0]   (k-pos t)
            // a1 = P[g+8][key 2t] = sacc[ks][2]
            // a2 = P[g][key 2t+1] = sacc[ks][1]   (k-pos t+4)
            // a3 = P[g+8][key2t+1]= sacc[ks][3]
#pragma unroll
            for (int ks = 0; ks < 4; ks++) {
                uint32_t a0 = __float_as_uint(sacc[ks][0]);
                uint32_t a1 = __float_as_uint(sacc[ks][2]);
                uint32_t a2 = __float_as_uint(sacc[ks][1]);
                uint32_t a3 = __float_as_uint(sacc[ks][3]);
#pragma unroll
                for (int df = 0; df < 4; df++) {
                    float2 vv = *(const float2*)&Vs[(df * 8 + g) * VSTR + nrow0 + ks * 8 + 2 * t];
                    mma_tf32(oacc[df][0], oacc[df][1], oacc[df][2], oacc[df][3],
                             a0, a1, a2, a3,
                             __float_as_uint(vv.x), __float_as_uint(vv.y));
                }
            }
        }

        if (c < 5) cp_wait0();
        __syncthreads();
    }

    // epilogue: normalize + store
    float inv0 = 1.f / l0, inv1 = 1.f / l1;
    if (r0 < NTOK) {
        float* orow = g_o + ((size_t)bb * NTOK + r0) * CDIM + h * HD;
#pragma unroll
        for (int df = 0; df < 4; df++)
            *(float2*)(orow + df * 8 + 2 * t) =
                make_float2(oacc[df][0] * inv0, oacc[df][1] * inv0);
    }
    if (r1 < NTOK) {
        float* orow = g_o + ((size_t)bb * NTOK + r1) * CDIM + h * HD;
#pragma unroll
        for (int df = 0; df < 4; df++)
            *(float2*)(orow + df * 8 + 2 * t) =
                make_float2(oacc[df][2] * inv1, oacc[df][3] * inv1);
    }
}

// ---------------------------------------------------------------------------
// Launch
// ---------------------------------------------------------------------------
extern "C" void kernel_launch(void* const* d_in, const int* in_sizes, int n_in,
                              void* d_out, int out_size) {
    const float* x      = (const float*)d_in[0];
    // d_in[1..3] = D,H,W scalars (constant 7) — unused
    const float* mask   = (const float*)d_in[4];
    const float* qg     = (const float*)d_in[5];
    const float* kv_w   = (const float*)d_in[6];
    const float* proj_w = (const float*)d_in[7];
    const float* proj_b = (const float*)d_in[8];
    const float* rpb    = (const float*)d_in[9];
    float* out = (float*)d_out;

    cudaFuncSetAttribute(attn_mma, cudaFuncAttributeMaxDynamicSharedMemorySize, ATT_SMEM);

    // 1) padded bias + mask tables
    bias_kernel<<<(NTOK * BMSTR + 255) / 256, 256>>>(rpb);
    mask_copy_kernel<<<(64 * NTOK * BMSTR + 255) / 256, 256>>>(mask);

    // 2) KV projection: [43904,512] x [1024,512]^T -> g_k (perm) / g_vT (transposed)
    gemm_tf32<<<dim3(1024 / 128, MROWS / 128), 256>>>(x, kv_w, nullptr, nullptr, 0);

    // 3) tensor-core flash attention -> g_o
    attn_mma<<<dim3(NB * NH, 3), 256, ATT_SMEM>>>(qg);

    // 4) output projection: [43904,512] x [512,512]^T + bias -> d_out (tf32 MMA)
    gemm_tf32<<<dim3(CDIM / 128, MROWS / 128), 256>>>(nullptr, proj_w, out, proj_b, 1);
}